// round 13
// baseline (speedup 1.0000x reference)
#include <cuda_runtime.h>
#include <mma.h>
#include <math.h>

using namespace nvcuda;

#define NN   50000
#define NP   50048
#define EE   400000
#define EP   450000
#define CIN  128
#define HID  64
#define HEADS 8
#define HC   512
#define OUTD 3

// ---------------- scratch ----------------
__device__ float g_ln[NP * HC];
__device__ float g_hw[NP * HC];
__device__ float g_h[NN * HC];
__device__ float g_alsrc[NN * HEADS];
__device__ float g_aldst[NN * HEADS];
__device__ float g_res[NN * OUTD];
__device__ int   g_deg[NN];
__device__ int   g_rowptr[NN + 1];
__device__ int   g_cursor[NN];
__device__ int   g_csrc[EP];

// ---------------- helpers ----------------
__device__ __forceinline__ void cpAsync16(unsigned dst, const void* src, int srcBytes) {
    asm volatile("cp.async.ca.shared.global [%0], [%1], 16, %2;"
                 :: "r"(dst), "l"(src), "r"(srcBytes));
}

__device__ __forceinline__ float gelu(float v) {
    return 0.5f * v * (1.0f + erff(v * 0.70710678118654752f));
}

// ---------------- CSR build ----------------
__global__ void zero_deg_kernel(int* deg) {
    int i = blockIdx.x * blockDim.x + threadIdx.x;
    if (i < NN) deg[i] = 0;
}

__global__ void deg_kernel(const int* __restrict__ ei, int* deg) {
    int e = blockIdx.x * blockDim.x + threadIdx.x;
    if (e >= EP) return;
    int dst = (e < EE) ? ei[EE + e] : e - EE;
    atomicAdd(&deg[dst], 1);
}

__global__ void scan_kernel(const int* __restrict__ deg, int* rowptr, int* cursor) {
    const int T = 1024;
    const int CH = (NN + T - 1) / T;
    int t = threadIdx.x;
    int base = t * CH;
    int s = 0;
    for (int i = 0; i < CH; i++) {
        int j = base + i;
        if (j < NN) s += deg[j];
    }
    __shared__ int sh[T];
    sh[t] = s;
    __syncthreads();
    for (int o = 1; o < T; o <<= 1) {
        int v = (t >= o) ? sh[t - o] : 0;
        __syncthreads();
        sh[t] += v;
        __syncthreads();
    }
    int run = (t > 0) ? sh[t - 1] : 0;
    for (int i = 0; i < CH; i++) {
        int j = base + i;
        if (j < NN) { rowptr[j] = run; cursor[j] = run; run += deg[j]; }
    }
    if (t == T - 1) rowptr[NN] = run;
}

__global__ void scatter_kernel(const int* __restrict__ ei, int* cursor, int* csrc) {
    int e = blockIdx.x * blockDim.x + threadIdx.x;
    if (e >= EP) return;
    int src, dst;
    if (e < EE) { src = ei[e]; dst = ei[EE + e]; } else { src = dst = e - EE; }
    int pos = atomicAdd(&cursor[dst], 1);
    csrc[pos] = src;
}

// ---------------- LayerNorm (raw input x only) ----------------
__global__ void ln_kernel(const float* __restrict__ x, const float* __restrict__ g,
                          const float* __restrict__ b, float* __restrict__ out, int ci) {
    int n = blockIdx.x;
    const float* row = x + (size_t)n * ci;
    float s1 = 0.f, s2 = 0.f;
    for (int k = threadIdx.x; k < ci; k += 128) {
        float v = row[k];
        s1 += v; s2 += v * v;
    }
    __shared__ float sh1[4], sh2[4];
    for (int o = 16; o > 0; o >>= 1) {
        s1 += __shfl_down_sync(0xffffffffu, s1, o);
        s2 += __shfl_down_sync(0xffffffffu, s2, o);
    }
    int w = threadIdx.x >> 5, l = threadIdx.x & 31;
    if (l == 0) { sh1[w] = s1; sh2[w] = s2; }
    __syncthreads();
    if (threadIdx.x == 0) {
        float a = 0.f, c = 0.f;
        for (int i = 0; i < 4; i++) { a += sh1[i]; c += sh2[i]; }
        sh1[0] = a; sh2[0] = c;
    }
    __syncthreads();
    float inv = 1.0f / (float)ci;
    float mean = sh1[0] * inv;
    float var  = sh2[0] * inv - mean * mean;
    float rstd = rsqrtf(var + 1e-6f);
    float* orow = out + (size_t)n * ci;
    for (int k = threadIdx.x; k < ci; k += 128)
        orow[k] = (row[k] - mean) * rstd * g[k] + b[k];
}

// ---------------- tf32 GEMM: 4-stage cp.async pipeline, ONE barrier/iter ----------------
#define BM 128
#define BN 128
#define BK 16
#define SPAD 4
#define SLD (BK + SPAD)   // 20 floats

__global__ void gemm_tf32(const float* __restrict__ A, const float* __restrict__ B,
                          float* __restrict__ C, int M, int K, int Nc,
                          const float* __restrict__ asr, const float* __restrict__ adt,
                          float* __restrict__ alsrc, float* __restrict__ aldst) {
    __shared__ __align__(16) float As[4][BM][SLD];
    __shared__ __align__(16) float Bs[4][BN][SLD];
    int tid = threadIdx.x;
    int warp = tid >> 5;
    int wm = warp >> 1;
    int wn = warp & 1;
    int rowBase = blockIdx.y * BM;
    int colBase = blockIdx.x * BN;

    int r = tid >> 2;
    int c = (tid & 3) * 4;

    wmma::fragment<wmma::accumulator, 16, 16, 8, float> acc[2][4];
    #pragma unroll
    for (int i = 0; i < 2; i++)
        #pragma unroll
        for (int j = 0; j < 4; j++) wmma::fill_fragment(acc[i][j], 0.f);

    int nIter = K / BK;   // >= 8 always (K=128 or 512)

    auto loadStage = [&](int s, int it) {
        int k0 = it * BK;
        #pragma unroll
        for (int i = 0; i < 2; i++) {
            int rr = r + i * 64;
            int gr = rowBase + rr;
            unsigned da = (unsigned)__cvta_generic_to_shared(&As[s][rr][c]);
            cpAsync16(da, A + (size_t)gr * K + k0 + c, gr < M ? 16 : 0);
            unsigned db = (unsigned)__cvta_generic_to_shared(&Bs[s][rr][c]);
            cpAsync16(db, B + (size_t)(colBase + rr) * K + k0 + c, 16);
        }
        asm volatile("cp.async.commit_group;");
    };

    loadStage(0, 0);
    loadStage(1, 1);
    loadStage(2, 2);

    for (int it = 0; it < nIter; it++) {
        int rem = nIter - 1 - it;
        if (rem >= 2)      asm volatile("cp.async.wait_group 2;");
        else if (rem == 1) asm volatile("cp.async.wait_group 1;");
        else               asm volatile("cp.async.wait_group 0;");
        __syncthreads();                         // data visible + prev compute done
        if (it + 3 < nIter) loadStage((it + 3) & 3, it + 3);  // overlaps compute
        int buf = it & 3;
        #pragma unroll
        for (int kk = 0; kk < BK; kk += 8) {
            wmma::fragment<wmma::matrix_a, 16, 16, 8, wmma::precision::tf32, wmma::row_major> af[2];
            wmma::fragment<wmma::matrix_b, 16, 16, 8, wmma::precision::tf32, wmma::col_major> bf[4];
            #pragma unroll
            for (int i = 0; i < 2; i++)
                wmma::load_matrix_sync(af[i], &As[buf][wm * 32 + i * 16][kk], SLD);
            #pragma unroll
            for (int j = 0; j < 4; j++)
                wmma::load_matrix_sync(bf[j], &Bs[buf][wn * 64 + j * 16][kk], SLD);
            #pragma unroll
            for (int i = 0; i < 2; i++)
                #pragma unroll
                for (int j = 0; j < 4; j++)
                    wmma::mma_sync(acc[i][j], af[i], bf[j], acc[i][j]);
        }
    }
    __syncthreads();
    #pragma unroll
    for (int i = 0; i < 2; i++)
        #pragma unroll
        for (int j = 0; j < 4; j++) {
            int rr = rowBase + wm * 32 + i * 16;
            int cc = colBase + wn * 64 + j * 16;
            wmma::store_matrix_sync(C + (size_t)rr * Nc + cc, acc[i][j], Nc, wmma::mem_row_major);
        }

    // ---- fused attn logits ----
    __threadfence_block();
    __syncthreads();
    int lane = tid & 31;
    int half = lane >> 4;
    int lc = (lane & 15) * 4;
    int head = (colBase >> 6) + half;
    float4 wa = *(const float4*)(asr + head * 64 + lc);
    float4 wd = *(const float4*)(adt + head * 64 + lc);
    #pragma unroll
    for (int rr = 0; rr < 16; rr++) {
        int grow = rowBase + warp * 16 + rr;
        float4 cv = *(const float4*)(C + (size_t)grow * Nc + colBase + half * 64 + lc);
        float s1 = cv.x * wa.x + cv.y * wa.y + cv.z * wa.z + cv.w * wa.w;
        float s2 = cv.x * wd.x + cv.y * wd.y + cv.z * wd.z + cv.w * wd.w;
        #pragma unroll
        for (int o = 8; o > 0; o >>= 1) {
            s1 += __shfl_xor_sync(0xffffffffu, s1, o);
            s2 += __shfl_xor_sync(0xffffffffu, s2, o);
        }
        if ((lane & 15) == 0 && grow < NN) {
            alsrc[grow * HEADS + head] = s1;
            aldst[grow * HEADS + head] = s2;
        }
    }
}

// ---------------- fused gather: softmax + agg + bias + gelu + residual + next-LN ----------------
__global__ void msgB_kernel(const int* __restrict__ rp, const int* __restrict__ csrc,
                            const float* __restrict__ alsrc, const float* __restrict__ aldst,
                            const float* __restrict__ hw, const float* __restrict__ bias,
                            const float* __restrict__ lg, const float* __restrict__ lb,
                            float* __restrict__ h, float* __restrict__ lnout, int addRes) {
    int dst = blockIdx.x;
    int tid = threadIdx.x;
    int hh = tid >> 4;
    int s0 = rp[dst], s1 = rp[dst + 1];
    float ad = __ldg(&aldst[dst * 8 + hh]);
    float4 acc = make_float4(0.f, 0.f, 0.f, 0.f);
    float esum = 0.f;
    for (int i = s0; i < s1; i++) {
        int src = __ldg(&csrc[i]);
        float al = __ldg(&alsrc[src * 8 + hh]);
        float v = al + ad;
        v = v > 0.f ? v : 0.2f * v;
        float e = expf(v);
        esum += e;
        float4 vv = *(const float4*)(hw + ((size_t)src << 9) + (tid << 2));
        acc.x += e * vv.x; acc.y += e * vv.y; acc.z += e * vv.z; acc.w += e * vv.w;
    }
    float siv = __frcp_rn(esum);
    acc.x *= siv; acc.y *= siv; acc.z *= siv; acc.w *= siv;
    float4 bb = *(const float4*)(bias + (tid << 2));
    float4 r;
    r.x = gelu(acc.x + bb.x);
    r.y = gelu(acc.y + bb.y);
    r.z = gelu(acc.z + bb.z);
    r.w = gelu(acc.w + bb.w);
    float* hrow = h + ((size_t)dst << 9) + (tid << 2);
    if (addRes) {
        float4 old = *(const float4*)hrow;
        r.x += old.x; r.y += old.y; r.z += old.z; r.w += old.w;
    }
    *(float4*)hrow = r;

    float p1 = r.x + r.y + r.z + r.w;
    float p2 = r.x * r.x + r.y * r.y + r.z * r.z + r.w * r.w;
    __shared__ float sh1[4], sh2[4];
    for (int o = 16; o > 0; o >>= 1) {
        p1 += __shfl_down_sync(0xffffffffu, p1, o);
        p2 += __shfl_down_sync(0xffffffffu, p2, o);
    }
    int w = tid >> 5, l = tid & 31;
    if (l == 0) { sh1[w] = p1; sh2[w] = p2; }
    __syncthreads();
    if (tid == 0) {
        sh1[0] = sh1[0] + sh1[1] + sh1[2] + sh1[3];
        sh2[0] = sh2[0] + sh2[1] + sh2[2] + sh2[3];
    }
    __syncthreads();
    float mean = sh1[0] * (1.0f / 512.0f);
    float var  = sh2[0] * (1.0f / 512.0f) - mean * mean;
    float rstd = rsqrtf(var + 1e-6f);
    float4 gg = *(const float4*)(lg + (tid << 2));
    float4 bv = *(const float4*)(lb + (tid << 2));
    float4 o4;
    o4.x = (r.x - mean) * rstd * gg.x + bv.x;
    o4.y = (r.y - mean) * rstd * gg.y + bv.y;
    o4.z = (r.z - mean) * rstd * gg.z + bv.z;
    o4.w = (r.w - mean) * rstd * gg.w + bv.w;
    *(float4*)(lnout + ((size_t)dst << 9) + (tid << 2)) = o4;
}

// ---------------- layer 3 tiny GEMM + logits ----------------
__global__ void gemm3_kernel(const float* __restrict__ ln, const float* __restrict__ W,
                             const float* __restrict__ asr, const float* __restrict__ adt,
                             float* hw3, float* alsrc, float* aldst) {
    int n = blockIdx.x, t = threadIdx.x;
    const float* row = ln + (size_t)n * 512;
    float p0 = 0.f, p1 = 0.f, p2 = 0.f;
    for (int k = t; k < 512; k += 128) {
        float a = row[k];
        p0 += a * W[k];
        p1 += a * W[512 + k];
        p2 += a * W[1024 + k];
    }
    __shared__ float sh[3][4];
    for (int o = 16; o > 0; o >>= 1) {
        p0 += __shfl_down_sync(0xffffffffu, p0, o);
        p1 += __shfl_down_sync(0xffffffffu, p1, o);
        p2 += __shfl_down_sync(0xffffffffu, p2, o);
    }
    int w = t >> 5, l = t & 31;
    if (l == 0) { sh[0][w] = p0; sh[1][w] = p1; sh[2][w] = p2; }
    __syncthreads();
    if (t == 0) {
        float v0 = sh[0][0] + sh[0][1] + sh[0][2] + sh[0][3];
        float v1 = sh[1][0] + sh[1][1] + sh[1][2] + sh[1][3];
        float v2 = sh[2][0] + sh[2][1] + sh[2][2] + sh[2][3];
        hw3[n * 3 + 0] = v0; hw3[n * 3 + 1] = v1; hw3[n * 3 + 2] = v2;
        alsrc[n] = v0 * asr[0] + v1 * asr[1] + v2 * asr[2];
        aldst[n] = v0 * adt[0] + v1 * adt[1] + v2 * adt[2];
    }
}

// ---------------- final gather ----------------
__global__ void final_gather(const int* __restrict__ rp, const int* __restrict__ csrc,
                             const float* __restrict__ alsrc, const float* __restrict__ aldst,
                             const float* __restrict__ hw3, const float* __restrict__ b3,
                             const float* __restrict__ res, float* __restrict__ out) {
    int dst = blockIdx.x * blockDim.x + threadIdx.x;
    if (dst >= NN) return;
    int s0 = rp[dst], s1 = rp[dst + 1];
    float ad = aldst[dst];
    float esum = 0.f;
    float a0 = 0.f, a1 = 0.f, a2 = 0.f;
    for (int i = s0; i < s1; i++) {
        int src = __ldg(&csrc[i]);
        float v = __ldg(&alsrc[src]) + ad;
        v = v > 0.f ? v : 0.2f * v;
        float e = expf(v);
        esum += e;
        a0 += e * __ldg(&hw3[src * 3 + 0]);
        a1 += e * __ldg(&hw3[src * 3 + 1]);
        a2 += e * __ldg(&hw3[src * 3 + 2]);
    }
    float siv = __frcp_rn(esum);
    out[dst * 3 + 0] = a0 * siv + b3[0] + res[dst * 3 + 0];
    out[dst * 3 + 1] = a1 * siv + b3[1] + res[dst * 3 + 1];
    out[dst * 3 + 2] = a2 * siv + b3[2] + res[dst * 3 + 2];
}

// ---------------- input residual ----------------
__global__ void resid_kernel(const float* __restrict__ x, const float* __restrict__ rw,
                             const float* __restrict__ rb, float* res) {
    int n = blockIdx.x, t = threadIdx.x;
    float a = x[(size_t)n * 128 + t];
    float p0 = a * rw[t], p1 = a * rw[128 + t], p2 = a * rw[256 + t];
    __shared__ float sh[3][4];
    for (int o = 16; o > 0; o >>= 1) {
        p0 += __shfl_down_sync(0xffffffffu, p0, o);
        p1 += __shfl_down_sync(0xffffffffu, p1, o);
        p2 += __shfl_down_sync(0xffffffffu, p2, o);
    }
    int w = t >> 5, l = t & 31;
    if (l == 0) { sh[0][w] = p0; sh[1][w] = p1; sh[2][w] = p2; }
    __syncthreads();
    if (t == 0) {
        res[n * 3 + 0] = sh[0][0] + sh[0][1] + sh[0][2] + sh[0][3] + rb[0];
        res[n * 3 + 1] = sh[1][0] + sh[1][1] + sh[1][2] + sh[1][3] + rb[1];
        res[n * 3 + 2] = sh[2][0] + sh[2][1] + sh[2][2] + sh[2][3] + rb[2];
    }
}

// ---------------- launch ----------------
extern "C" void kernel_launch(void* const* d_in, const int* in_sizes, int n_in,
                              void* d_out, int out_size) {
    const float* x    = (const float*)d_in[0];
    const int*   ei   = (const int*)d_in[1];
    const float* resW = (const float*)d_in[2];
    const float* resb = (const float*)d_in[3];

    const float* lng[4];  const float* lnb[4];
    const float* Wl[4];   const float* asr[4];
    const float* adt[4];  const float* bl[4];
    for (int l = 0; l < 4; l++) {
        int base = 4 + 6 * l;
        lng[l] = (const float*)d_in[base + 0];
        lnb[l] = (const float*)d_in[base + 1];
        Wl[l]  = (const float*)d_in[base + 2];
        asr[l] = (const float*)d_in[base + 3];
        adt[l] = (const float*)d_in[base + 4];
        bl[l]  = (const float*)d_in[base + 5];
    }

    float *ln_, *hw_, *h_, *alsrc_, *aldst_, *res_;
    int *deg_, *rp_, *cur_, *csrc_;
    cudaGetSymbolAddress((void**)&ln_,    g_ln);
    cudaGetSymbolAddress((void**)&hw_,    g_hw);
    cudaGetSymbolAddress((void**)&h_,     g_h);
    cudaGetSymbolAddress((void**)&alsrc_, g_alsrc);
    cudaGetSymbolAddress((void**)&aldst_, g_aldst);
    cudaGetSymbolAddress((void**)&res_,   g_res);
    cudaGetSymbolAddress((void**)&deg_,   g_deg);
    cudaGetSymbolAddress((void**)&rp_,    g_rowptr);
    cudaGetSymbolAddress((void**)&cur_,   g_cursor);
    cudaGetSymbolAddress((void**)&csrc_,  g_csrc);

    // launch order: ncu capture (launch #4) lands on gemm_tf32
    resid_kernel<<<NN, 128>>>(x, resW, resb, res_);                       // 1
    ln_kernel<<<NN, 128>>>(x, lng[0], lnb[0], ln_, CIN);                  // 2
    zero_deg_kernel<<<(NN + 255) / 256, 256>>>(deg_);                     // 3
    gemm_tf32<<<dim3(HC / BN, NP / BM), 256>>>(ln_, Wl[0], hw_, NN, CIN, HC,
                                               asr[0], adt[0], alsrc_, aldst_);  // 4 <- profiled
    deg_kernel<<<(EP + 255) / 256, 256>>>(ei, deg_);                      // 5
    scan_kernel<<<1, 1024>>>(deg_, rp_, cur_);                            // 6
    scatter_kernel<<<(EP + 255) / 256, 256>>>(ei, cur_, csrc_);           // 7

    msgB_kernel<<<NN, 128>>>(rp_, csrc_, alsrc_, aldst_, hw_, bl[0],
                             lng[1], lnb[1], h_, ln_, 0);

    for (int l = 1; l < 3; l++) {
        gemm_tf32<<<dim3(HC / BN, NP / BM), 256>>>(ln_, Wl[l], hw_, NN, HC, HC,
                                                   asr[l], adt[l], alsrc_, aldst_);
        msgB_kernel<<<NN, 128>>>(rp_, csrc_, alsrc_, aldst_, hw_, bl[l],
                                 lng[l + 1], lnb[l + 1], h_, ln_, 1);
    }

    gemm3_kernel<<<NN, 128>>>(ln_, Wl[3], asr[3], adt[3], hw_, alsrc_, aldst_);
    final_gather<<<(NN + 255) / 256, 256>>>(rp_, csrc_, alsrc_, aldst_, hw_, bl[3], res_, (float*)d_out);
}

// round 14
// speedup vs baseline: 1.0135x; 1.0135x over previous
#include <cuda_runtime.h>
#include <mma.h>
#include <math.h>

using namespace nvcuda;

#define NN   50000
#define NP   50048
#define EE   400000
#define EP   450000
#define CIN  128
#define HID  64
#define HEADS 8
#define HC   512
#define OUTD 3

// ---------------- scratch ----------------
__device__ float g_ln[NP * HC];
__device__ float g_hw[NP * HC];
__device__ float g_h[NN * HC];
__device__ float g_alsrc[NN * HEADS];
__device__ float g_aldst[NN * HEADS];
__device__ float g_res[NN * OUTD];
__device__ int   g_deg[NN];
__device__ int   g_rowptr[NN + 1];
__device__ int   g_cursor[NN];
__device__ int   g_csrc[EP];

// ---------------- helpers ----------------
__device__ __forceinline__ void cpAsync16(unsigned dst, const void* src, int srcBytes) {
    asm volatile("cp.async.cg.shared.global [%0], [%1], 16, %2;"
                 :: "r"(dst), "l"(src), "r"(srcBytes));
}

__device__ __forceinline__ float gelu(float v) {
    return 0.5f * v * (1.0f + erff(v * 0.70710678118654752f));
}

// ---------------- CSR build ----------------
__global__ void zero_deg_kernel(int* deg) {
    int i = blockIdx.x * blockDim.x + threadIdx.x;
    if (i < NN) deg[i] = 0;
}

__global__ void deg_kernel(const int* __restrict__ ei, int* deg) {
    int e = blockIdx.x * blockDim.x + threadIdx.x;
    if (e >= EP) return;
    int dst = (e < EE) ? ei[EE + e] : e - EE;
    atomicAdd(&deg[dst], 1);
}

__global__ void scan_kernel(const int* __restrict__ deg, int* rowptr, int* cursor) {
    const int T = 1024;
    const int CH = (NN + T - 1) / T;
    int t = threadIdx.x;
    int base = t * CH;
    int s = 0;
    for (int i = 0; i < CH; i++) {
        int j = base + i;
        if (j < NN) s += deg[j];
    }
    __shared__ int sh[T];
    sh[t] = s;
    __syncthreads();
    for (int o = 1; o < T; o <<= 1) {
        int v = (t >= o) ? sh[t - o] : 0;
        __syncthreads();
        sh[t] += v;
        __syncthreads();
    }
    int run = (t > 0) ? sh[t - 1] : 0;
    for (int i = 0; i < CH; i++) {
        int j = base + i;
        if (j < NN) { rowptr[j] = run; cursor[j] = run; run += deg[j]; }
    }
    if (t == T - 1) rowptr[NN] = run;
}

__global__ void scatter_kernel(const int* __restrict__ ei, int* cursor, int* csrc) {
    int e = blockIdx.x * blockDim.x + threadIdx.x;
    if (e >= EP) return;
    int src, dst;
    if (e < EE) { src = ei[e]; dst = ei[EE + e]; } else { src = dst = e - EE; }
    int pos = atomicAdd(&cursor[dst], 1);
    csrc[pos] = src;
}

// ---------------- LayerNorm (raw input x only) ----------------
__global__ void ln_kernel(const float* __restrict__ x, const float* __restrict__ g,
                          const float* __restrict__ b, float* __restrict__ out, int ci) {
    int n = blockIdx.x;
    const float* row = x + (size_t)n * ci;
    float s1 = 0.f, s2 = 0.f;
    for (int k = threadIdx.x; k < ci; k += 128) {
        float v = row[k];
        s1 += v; s2 += v * v;
    }
    __shared__ float sh1[4], sh2[4];
    for (int o = 16; o > 0; o >>= 1) {
        s1 += __shfl_down_sync(0xffffffffu, s1, o);
        s2 += __shfl_down_sync(0xffffffffu, s2, o);
    }
    int w = threadIdx.x >> 5, l = threadIdx.x & 31;
    if (l == 0) { sh1[w] = s1; sh2[w] = s2; }
    __syncthreads();
    if (threadIdx.x == 0) {
        float a = 0.f, c = 0.f;
        for (int i = 0; i < 4; i++) { a += sh1[i]; c += sh2[i]; }
        sh1[0] = a; sh2[0] = c;
    }
    __syncthreads();
    float inv = 1.0f / (float)ci;
    float mean = sh1[0] * inv;
    float var  = sh2[0] * inv - mean * mean;
    float rstd = rsqrtf(var + 1e-6f);
    float* orow = out + (size_t)n * ci;
    for (int k = threadIdx.x; k < ci; k += 128)
        orow[k] = (row[k] - mean) * rstd * g[k] + b[k];
}

// ---------------- tf32 GEMM (R12: 2-stage, SLD=20, issue-before-wait) ----------------
#define BM 128
#define BN 128
#define BK 16
#define SPAD 4
#define SLD (BK + SPAD)   // 20 floats

__global__ void gemm_tf32(const float* __restrict__ A, const float* __restrict__ B,
                          float* __restrict__ C, int M, int K, int Nc,
                          const float* __restrict__ asr, const float* __restrict__ adt,
                          float* __restrict__ alsrc, float* __restrict__ aldst) {
    __shared__ __align__(16) float As[2][BM][SLD];
    __shared__ __align__(16) float Bs[2][BN][SLD];
    int tid = threadIdx.x;
    int warp = tid >> 5;
    int wm = warp >> 1;
    int wn = warp & 1;
    int rowBase = blockIdx.y * BM;
    int colBase = blockIdx.x * BN;

    int r = tid >> 2;
    int c = (tid & 3) * 4;

    wmma::fragment<wmma::accumulator, 16, 16, 8, float> acc[2][4];
    #pragma unroll
    for (int i = 0; i < 2; i++)
        #pragma unroll
        for (int j = 0; j < 4; j++) wmma::fill_fragment(acc[i][j], 0.f);

    int nIter = K / BK;

    auto loadStage = [&](int s, int it) {
        int k0 = it * BK;
        #pragma unroll
        for (int i = 0; i < 2; i++) {
            int rr = r + i * 64;
            int gr = rowBase + rr;
            unsigned da = (unsigned)__cvta_generic_to_shared(&As[s][rr][c]);
            cpAsync16(da, A + (size_t)gr * K + k0 + c, gr < M ? 16 : 0);
            unsigned db = (unsigned)__cvta_generic_to_shared(&Bs[s][rr][c]);
            cpAsync16(db, B + (size_t)(colBase + rr) * K + k0 + c, 16);
        }
        asm volatile("cp.async.commit_group;");
    };

    loadStage(0, 0);

    for (int it = 0; it < nIter; it++) {
        int buf = it & 1;
        if (it + 1 < nIter) {
            loadStage(buf ^ 1, it + 1);
            asm volatile("cp.async.wait_group 1;");
        } else {
            asm volatile("cp.async.wait_group 0;");
        }
        __syncthreads();
        #pragma unroll
        for (int kk = 0; kk < BK; kk += 8) {
            wmma::fragment<wmma::matrix_a, 16, 16, 8, wmma::precision::tf32, wmma::row_major> af[2];
            wmma::fragment<wmma::matrix_b, 16, 16, 8, wmma::precision::tf32, wmma::col_major> bf[4];
            #pragma unroll
            for (int i = 0; i < 2; i++)
                wmma::load_matrix_sync(af[i], &As[buf][wm * 32 + i * 16][kk], SLD);
            #pragma unroll
            for (int j = 0; j < 4; j++)
                wmma::load_matrix_sync(bf[j], &Bs[buf][wn * 64 + j * 16][kk], SLD);
            #pragma unroll
            for (int i = 0; i < 2; i++)
                #pragma unroll
                for (int j = 0; j < 4; j++)
                    wmma::mma_sync(acc[i][j], af[i], bf[j], acc[i][j]);
        }
        __syncthreads();
    }
    #pragma unroll
    for (int i = 0; i < 2; i++)
        #pragma unroll
        for (int j = 0; j < 4; j++) {
            int rr = rowBase + wm * 32 + i * 16;
            int cc = colBase + wn * 64 + j * 16;
            wmma::store_matrix_sync(C + (size_t)rr * Nc + cc, acc[i][j], Nc, wmma::mem_row_major);
        }

    // ---- fused attn logits ----
    __threadfence_block();
    __syncthreads();
    int lane = tid & 31;
    int half = lane >> 4;
    int lc = (lane & 15) * 4;
    int head = (colBase >> 6) + half;
    float4 wa = *(const float4*)(asr + head * 64 + lc);
    float4 wd = *(const float4*)(adt + head * 64 + lc);
    #pragma unroll
    for (int rr = 0; rr < 16; rr++) {
        int grow = rowBase + warp * 16 + rr;
        float4 cv = *(const float4*)(C + (size_t)grow * Nc + colBase + half * 64 + lc);
        float s1 = cv.x * wa.x + cv.y * wa.y + cv.z * wa.z + cv.w * wa.w;
        float s2 = cv.x * wd.x + cv.y * wd.y + cv.z * wd.z + cv.w * wd.w;
        #pragma unroll
        for (int o = 8; o > 0; o >>= 1) {
            s1 += __shfl_xor_sync(0xffffffffu, s1, o);
            s2 += __shfl_xor_sync(0xffffffffu, s2, o);
        }
        if ((lane & 15) == 0 && grow < NN) {
            alsrc[grow * HEADS + head] = s1;
            aldst[grow * HEADS + head] = s2;
        }
    }
}

// ---------------- fused gather: softmax + agg + bias + gelu + residual + next-LN ----------------
__global__ void msgB_kernel(const int* __restrict__ rp, const int* __restrict__ csrc,
                            const float* __restrict__ alsrc, const float* __restrict__ aldst,
                            const float* __restrict__ hw, const float* __restrict__ bias,
                            const float* __restrict__ lg, const float* __restrict__ lb,
                            float* __restrict__ h, float* __restrict__ lnout, int addRes) {
    int dst = blockIdx.x;
    int tid = threadIdx.x;
    int hh = tid >> 4;
    int s0 = rp[dst], s1 = rp[dst + 1];
    float ad = __ldg(&aldst[dst * 8 + hh]);
    float4 acc = make_float4(0.f, 0.f, 0.f, 0.f);
    float esum = 0.f;
    for (int i = s0; i < s1; i++) {
        int src = __ldg(&csrc[i]);
        float al = __ldg(&alsrc[src * 8 + hh]);
        float v = al + ad;
        v = v > 0.f ? v : 0.2f * v;
        float e = expf(v);
        esum += e;
        float4 vv = *(const float4*)(hw + ((size_t)src << 9) + (tid << 2));
        acc.x += e * vv.x; acc.y += e * vv.y; acc.z += e * vv.z; acc.w += e * vv.w;
    }
    float siv = __frcp_rn(esum);
    acc.x *= siv; acc.y *= siv; acc.z *= siv; acc.w *= siv;
    float4 bb = *(const float4*)(bias + (tid << 2));
    float4 r;
    r.x = gelu(acc.x + bb.x);
    r.y = gelu(acc.y + bb.y);
    r.z = gelu(acc.z + bb.z);
    r.w = gelu(acc.w + bb.w);
    float* hrow = h + ((size_t)dst << 9) + (tid << 2);
    if (addRes) {
        float4 old = *(const float4*)hrow;
        r.x += old.x; r.y += old.y; r.z += old.z; r.w += old.w;
    }
    *(float4*)hrow = r;

    float p1 = r.x + r.y + r.z + r.w;
    float p2 = r.x * r.x + r.y * r.y + r.z * r.z + r.w * r.w;
    __shared__ float sh1[4], sh2[4];
    for (int o = 16; o > 0; o >>= 1) {
        p1 += __shfl_down_sync(0xffffffffu, p1, o);
        p2 += __shfl_down_sync(0xffffffffu, p2, o);
    }
    int w = tid >> 5, l = tid & 31;
    if (l == 0) { sh1[w] = p1; sh2[w] = p2; }
    __syncthreads();
    if (tid == 0) {
        sh1[0] = sh1[0] + sh1[1] + sh1[2] + sh1[3];
        sh2[0] = sh2[0] + sh2[1] + sh2[2] + sh2[3];
    }
    __syncthreads();
    float mean = sh1[0] * (1.0f / 512.0f);
    float var  = sh2[0] * (1.0f / 512.0f) - mean * mean;
    float rstd = rsqrtf(var + 1e-6f);
    float4 gg = *(const float4*)(lg + (tid << 2));
    float4 bv = *(const float4*)(lb + (tid << 2));
    float4 o4;
    o4.x = (r.x - mean) * rstd * gg.x + bv.x;
    o4.y = (r.y - mean) * rstd * gg.y + bv.y;
    o4.z = (r.z - mean) * rstd * gg.z + bv.z;
    o4.w = (r.w - mean) * rstd * gg.w + bv.w;
    *(float4*)(lnout + ((size_t)dst << 9) + (tid << 2)) = o4;
}

// ---------------- layer 3 tiny GEMM + logits ----------------
__global__ void gemm3_kernel(const float* __restrict__ ln, const float* __restrict__ W,
                             const float* __restrict__ asr, const float* __restrict__ adt,
                             float* hw3, float* alsrc, float* aldst) {
    int n = blockIdx.x, t = threadIdx.x;
    const float* row = ln + (size_t)n * 512;
    float p0 = 0.f, p1 = 0.f, p2 = 0.f;
    for (int k = t; k < 512; k += 128) {
        float a = row[k];
        p0 += a * W[k];
        p1 += a * W[512 + k];
        p2 += a * W[1024 + k];
    }
    __shared__ float sh[3][4];
    for (int o = 16; o > 0; o >>= 1) {
        p0 += __shfl_down_sync(0xffffffffu, p0, o);
        p1 += __shfl_down_sync(0xffffffffu, p1, o);
        p2 += __shfl_down_sync(0xffffffffu, p2, o);
    }
    int w = t >> 5, l = t & 31;
    if (l == 0) { sh[0][w] = p0; sh[1][w] = p1; sh[2][w] = p2; }
    __syncthreads();
    if (t == 0) {
        float v0 = sh[0][0] + sh[0][1] + sh[0][2] + sh[0][3];
        float v1 = sh[1][0] + sh[1][1] + sh[1][2] + sh[1][3];
        float v2 = sh[2][0] + sh[2][1] + sh[2][2] + sh[2][3];
        hw3[n * 3 + 0] = v0; hw3[n * 3 + 1] = v1; hw3[n * 3 + 2] = v2;
        alsrc[n] = v0 * asr[0] + v1 * asr[1] + v2 * asr[2];
        aldst[n] = v0 * adt[0] + v1 * adt[1] + v2 * adt[2];
    }
}

// ---------------- final gather ----------------
__global__ void final_gather(const int* __restrict__ rp, const int* __restrict__ csrc,
                             const float* __restrict__ alsrc, const float* __restrict__ aldst,
                             const float* __restrict__ hw3, const float* __restrict__ b3,
                             const float* __restrict__ res, float* __restrict__ out) {
    int dst = blockIdx.x * blockDim.x + threadIdx.x;
    if (dst >= NN) return;
    int s0 = rp[dst], s1 = rp[dst + 1];
    float ad = aldst[dst];
    float esum = 0.f;
    float a0 = 0.f, a1 = 0.f, a2 = 0.f;
    for (int i = s0; i < s1; i++) {
        int src = __ldg(&csrc[i]);
        float v = __ldg(&alsrc[src]) + ad;
        v = v > 0.f ? v : 0.2f * v;
        float e = expf(v);
        esum += e;
        a0 += e * __ldg(&hw3[src * 3 + 0]);
        a1 += e * __ldg(&hw3[src * 3 + 1]);
        a2 += e * __ldg(&hw3[src * 3 + 2]);
    }
    float siv = __frcp_rn(esum);
    out[dst * 3 + 0] = a0 * siv + b3[0] + res[dst * 3 + 0];
    out[dst * 3 + 1] = a1 * siv + b3[1] + res[dst * 3 + 1];
    out[dst * 3 + 2] = a2 * siv + b3[2] + res[dst * 3 + 2];
}

// ---------------- input residual ----------------
__global__ void resid_kernel(const float* __restrict__ x, const float* __restrict__ rw,
                             const float* __restrict__ rb, float* res) {
    int n = blockIdx.x, t = threadIdx.x;
    float a = x[(size_t)n * 128 + t];
    float p0 = a * rw[t], p1 = a * rw[128 + t], p2 = a * rw[256 + t];
    __shared__ float sh[3][4];
    for (int o = 16; o > 0; o >>= 1) {
        p0 += __shfl_down_sync(0xffffffffu, p0, o);
        p1 += __shfl_down_sync(0xffffffffu, p1, o);
        p2 += __shfl_down_sync(0xffffffffu, p2, o);
    }
    int w = t >> 5, l = t & 31;
    if (l == 0) { sh[0][w] = p0; sh[1][w] = p1; sh[2][w] = p2; }
    __syncthreads();
    if (t == 0) {
        res[n * 3 + 0] = sh[0][0] + sh[0][1] + sh[0][2] + sh[0][3] + rb[0];
        res[n * 3 + 1] = sh[1][0] + sh[1][1] + sh[1][2] + sh[1][3] + rb[1];
        res[n * 3 + 2] = sh[2][0] + sh[2][1] + sh[2][2] + sh[2][3] + rb[2];
    }
}

// ---------------- launch ----------------
extern "C" void kernel_launch(void* const* d_in, const int* in_sizes, int n_in,
                              void* d_out, int out_size) {
    const float* x    = (const float*)d_in[0];
    const int*   ei   = (const int*)d_in[1];
    const float* resW = (const float*)d_in[2];
    const float* resb = (const float*)d_in[3];

    const float* lng[4];  const float* lnb[4];
    const float* Wl[4];   const float* asr[4];
    const float* adt[4];  const float* bl[4];
    for (int l = 0; l < 4; l++) {
        int base = 4 + 6 * l;
        lng[l] = (const float*)d_in[base + 0];
        lnb[l] = (const float*)d_in[base + 1];
        Wl[l]  = (const float*)d_in[base + 2];
        asr[l] = (const float*)d_in[base + 3];
        adt[l] = (const float*)d_in[base + 4];
        bl[l]  = (const float*)d_in[base + 5];
    }

    float *ln_, *hw_, *h_, *alsrc_, *aldst_, *res_;
    int *deg_, *rp_, *cur_, *csrc_;
    cudaGetSymbolAddress((void**)&ln_,    g_ln);
    cudaGetSymbolAddress((void**)&hw_,    g_hw);
    cudaGetSymbolAddress((void**)&h_,     g_h);
    cudaGetSymbolAddress((void**)&alsrc_, g_alsrc);
    cudaGetSymbolAddress((void**)&aldst_, g_aldst);
    cudaGetSymbolAddress((void**)&res_,   g_res);
    cudaGetSymbolAddress((void**)&deg_,   g_deg);
    cudaGetSymbolAddress((void**)&rp_,    g_rowptr);
    cudaGetSymbolAddress((void**)&cur_,   g_cursor);
    cudaGetSymbolAddress((void**)&csrc_,  g_csrc);

    // launch order: ncu capture (launch #4) lands on gemm_tf32
    resid_kernel<<<NN, 128>>>(x, resW, resb, res_);                       // 1
    ln_kernel<<<NN, 128>>>(x, lng[0], lnb[0], ln_, CIN);                  // 2
    zero_deg_kernel<<<(NN + 255) / 256, 256>>>(deg_);                     // 3
    gemm_tf32<<<dim3(HC / BN, NP / BM), 256>>>(ln_, Wl[0], hw_, NN, CIN, HC,
                                               asr[0], adt[0], alsrc_, aldst_);  // 4 <- profiled
    deg_kernel<<<(EP + 255) / 256, 256>>>(ei, deg_);                      // 5
    scan_kernel<<<1, 1024>>>(deg_, rp_, cur_);                            // 6
    scatter_kernel<<<(EP + 255) / 256, 256>>>(ei, cur_, csrc_);           // 7

    msgB_kernel<<<NN, 128>>>(rp_, csrc_, alsrc_, aldst_, hw_, bl[0],
                             lng[1], lnb[1], h_, ln_, 0);

    for (int l = 1; l < 3; l++) {
        gemm_tf32<<<dim3(HC / BN, NP / BM), 256>>>(ln_, Wl[l], hw_, NN, HC, HC,
                                                   asr[l], adt[l], alsrc_, aldst_);
        msgB_kernel<<<NN, 128>>>(rp_, csrc_, alsrc_, aldst_, hw_, bl[l],
                                 lng[l + 1], lnb[l + 1], h_, ln_, 1);
    }

    gemm3_kernel<<<NN, 128>>>(ln_, Wl[3], asr[3], adt[3], hw_, alsrc_, aldst_);
    final_gather<<<(NN + 255) / 256, 256>>>(rp_, csrc_, alsrc_, aldst_, hw_, bl[3], res_, (float*)d_out);
}

// round 15
// speedup vs baseline: 1.0648x; 1.0506x over previous
#include <cuda_runtime.h>
#include <mma.h>
#include <math.h>

using namespace nvcuda;

#define NN   50000
#define NP   50048
#define EE   400000
#define EP   450000
#define CIN  128
#define HID  64
#define HEADS 8
#define HC   512
#define OUTD 3

// ---------------- scratch ----------------
__device__ float g_ln[NP * HC];
__device__ float g_hw[NP * HC];
__device__ float g_h[NN * HC];
__device__ float g_alsrc[NN * HEADS];
__device__ float g_aldst[NN * HEADS];
__device__ float g_res[NN * OUTD];
__device__ int   g_deg[NN];
__device__ int   g_rowptr[NN + 1];
__device__ int   g_cursor[NN];
__device__ int   g_csrc[EP];

// ---------------- helpers ----------------
__device__ __forceinline__ void cpAsync16(unsigned dst, const void* src, int srcBytes) {
    asm volatile("cp.async.ca.shared.global [%0], [%1], 16, %2;"
                 :: "r"(dst), "l"(src), "r"(srcBytes));
}

__device__ __forceinline__ float gelu(float v) {
    return 0.5f * v * (1.0f + erff(v * 0.70710678118654752f));
}

// ---------------- CSR build ----------------
__global__ void zero_deg_kernel(int* deg) {
    int i = blockIdx.x * blockDim.x + threadIdx.x;
    if (i < NN) deg[i] = 0;
}

__global__ void deg_kernel(const int* __restrict__ ei, int* deg) {
    int e = blockIdx.x * blockDim.x + threadIdx.x;
    if (e >= EP) return;
    int dst = (e < EE) ? ei[EE + e] : e - EE;
    atomicAdd(&deg[dst], 1);
}

__global__ void scan_kernel(const int* __restrict__ deg, int* rowptr, int* cursor) {
    const int T = 1024;
    const int CH = (NN + T - 1) / T;
    int t = threadIdx.x;
    int base = t * CH;
    int s = 0;
    for (int i = 0; i < CH; i++) {
        int j = base + i;
        if (j < NN) s += deg[j];
    }
    __shared__ int sh[T];
    sh[t] = s;
    __syncthreads();
    for (int o = 1; o < T; o <<= 1) {
        int v = (t >= o) ? sh[t - o] : 0;
        __syncthreads();
        sh[t] += v;
        __syncthreads();
    }
    int run = (t > 0) ? sh[t - 1] : 0;
    for (int i = 0; i < CH; i++) {
        int j = base + i;
        if (j < NN) { rowptr[j] = run; cursor[j] = run; run += deg[j]; }
    }
    if (t == T - 1) rowptr[NN] = run;
}

__global__ void scatter_kernel(const int* __restrict__ ei, int* cursor, int* csrc) {
    int e = blockIdx.x * blockDim.x + threadIdx.x;
    if (e >= EP) return;
    int src, dst;
    if (e < EE) { src = ei[e]; dst = ei[EE + e]; } else { src = dst = e - EE; }
    int pos = atomicAdd(&cursor[dst], 1);
    csrc[pos] = src;
}

// ---------------- LayerNorm (raw input x only) ----------------
__global__ void ln_kernel(const float* __restrict__ x, const float* __restrict__ g,
                          const float* __restrict__ b, float* __restrict__ out, int ci) {
    int n = blockIdx.x;
    const float* row = x + (size_t)n * ci;
    float s1 = 0.f, s2 = 0.f;
    for (int k = threadIdx.x; k < ci; k += 128) {
        float v = row[k];
        s1 += v; s2 += v * v;
    }
    __shared__ float sh1[4], sh2[4];
    for (int o = 16; o > 0; o >>= 1) {
        s1 += __shfl_down_sync(0xffffffffu, s1, o);
        s2 += __shfl_down_sync(0xffffffffu, s2, o);
    }
    int w = threadIdx.x >> 5, l = threadIdx.x & 31;
    if (l == 0) { sh1[w] = s1; sh2[w] = s2; }
    __syncthreads();
    if (threadIdx.x == 0) {
        float a = 0.f, c = 0.f;
        for (int i = 0; i < 4; i++) { a += sh1[i]; c += sh2[i]; }
        sh1[0] = a; sh2[0] = c;
    }
    __syncthreads();
    float inv = 1.0f / (float)ci;
    float mean = sh1[0] * inv;
    float var  = sh2[0] * inv - mean * mean;
    float rstd = rsqrtf(var + 1e-6f);
    float* orow = out + (size_t)n * ci;
    for (int k = threadIdx.x; k < ci; k += 128)
        orow[k] = (row[k] - mean) * rstd * g[k] + b[k];
}

// ---------------- tf32 GEMM: 128 threads, 4 warps x (64x64), 2-stage cp.async ----------------
#define BM 128
#define BN 128
#define BK 16
#define SPAD 4
#define SLD (BK + SPAD)   // 20 floats

__global__ void __launch_bounds__(128, 2) gemm_tf32(
                          const float* __restrict__ A, const float* __restrict__ B,
                          float* __restrict__ C, int M, int K, int Nc,
                          const float* __restrict__ asr, const float* __restrict__ adt,
                          float* __restrict__ alsrc, float* __restrict__ aldst) {
    __shared__ __align__(16) float As[2][BM][SLD];
    __shared__ __align__(16) float Bs[2][BN][SLD];
    int tid = threadIdx.x;
    int warp = tid >> 5;
    int wm = warp >> 1;      // 0..1 -> 64-row strip
    int wn = warp & 1;       // 0..1 -> 64-col strip
    int rowBase = blockIdx.y * BM;
    int colBase = blockIdx.x * BN;

    wmma::fragment<wmma::accumulator, 16, 16, 8, float> acc[4][4];
    #pragma unroll
    for (int i = 0; i < 4; i++)
        #pragma unroll
        for (int j = 0; j < 4; j++) wmma::fill_fragment(acc[i][j], 0.f);

    int nIter = K / BK;

    // tile = 128x16 = 512 float4 per matrix; 128 threads -> 4 each
    int r = tid >> 2;            // 0..31 (+32/64/96)
    int c = (tid & 3) * 4;
    auto loadStage = [&](int s, int it) {
        int k0 = it * BK;
        #pragma unroll
        for (int i = 0; i < 4; i++) {
            int rr = r + i * 32;
            int gr = rowBase + rr;
            unsigned da = (unsigned)__cvta_generic_to_shared(&As[s][rr][c]);
            cpAsync16(da, A + (size_t)gr * K + k0 + c, gr < M ? 16 : 0);
            unsigned db = (unsigned)__cvta_generic_to_shared(&Bs[s][rr][c]);
            cpAsync16(db, B + (size_t)(colBase + rr) * K + k0 + c, 16);
        }
        asm volatile("cp.async.commit_group;");
    };

    loadStage(0, 0);

    for (int it = 0; it < nIter; it++) {
        int buf = it & 1;
        if (it + 1 < nIter) {
            loadStage(buf ^ 1, it + 1);
            asm volatile("cp.async.wait_group 1;");
        } else {
            asm volatile("cp.async.wait_group 0;");
        }
        __syncthreads();
        #pragma unroll
        for (int kk = 0; kk < BK; kk += 8) {
            wmma::fragment<wmma::matrix_a, 16, 16, 8, wmma::precision::tf32, wmma::row_major> af[4];
            wmma::fragment<wmma::matrix_b, 16, 16, 8, wmma::precision::tf32, wmma::col_major> bf[4];
            #pragma unroll
            for (int i = 0; i < 4; i++)
                wmma::load_matrix_sync(af[i], &As[buf][wm * 64 + i * 16][kk], SLD);
            #pragma unroll
            for (int j = 0; j < 4; j++)
                wmma::load_matrix_sync(bf[j], &Bs[buf][wn * 64 + j * 16][kk], SLD);
            #pragma unroll
            for (int i = 0; i < 4; i++)
                #pragma unroll
                for (int j = 0; j < 4; j++)
                    wmma::mma_sync(acc[i][j], af[i], bf[j], acc[i][j]);
        }
        __syncthreads();
    }
    #pragma unroll
    for (int i = 0; i < 4; i++)
        #pragma unroll
        for (int j = 0; j < 4; j++) {
            int rr = rowBase + wm * 64 + i * 16;
            int cc = colBase + wn * 64 + j * 16;
            wmma::store_matrix_sync(C + (size_t)rr * Nc + cc, acc[i][j], Nc, wmma::mem_row_major);
        }

    // ---- fused attn logits: 4 warps x 32 rows ----
    __threadfence_block();
    __syncthreads();
    int lane = tid & 31;
    int half = lane >> 4;
    int lc = (lane & 15) * 4;
    int head = (colBase >> 6) + half;
    float4 wa = *(const float4*)(asr + head * 64 + lc);
    float4 wd = *(const float4*)(adt + head * 64 + lc);
    #pragma unroll
    for (int rr = 0; rr < 32; rr++) {
        int grow = rowBase + warp * 32 + rr;
        float4 cv = *(const float4*)(C + (size_t)grow * Nc + colBase + half * 64 + lc);
        float s1 = cv.x * wa.x + cv.y * wa.y + cv.z * wa.z + cv.w * wa.w;
        float s2 = cv.x * wd.x + cv.y * wd.y + cv.z * wd.z + cv.w * wd.w;
        #pragma unroll
        for (int o = 8; o > 0; o >>= 1) {
            s1 += __shfl_xor_sync(0xffffffffu, s1, o);
            s2 += __shfl_xor_sync(0xffffffffu, s2, o);
        }
        if ((lane & 15) == 0 && grow < NN) {
            alsrc[grow * HEADS + head] = s1;
            aldst[grow * HEADS + head] = s2;
        }
    }
}

// ---------------- fused gather: softmax + agg + bias + gelu + residual + next-LN ----------------
__global__ void msgB_kernel(const int* __restrict__ rp, const int* __restrict__ csrc,
                            const float* __restrict__ alsrc, const float* __restrict__ aldst,
                            const float* __restrict__ hw, const float* __restrict__ bias,
                            const float* __restrict__ lg, const float* __restrict__ lb,
                            float* __restrict__ h, float* __restrict__ lnout, int addRes) {
    int dst = blockIdx.x;
    int tid = threadIdx.x;
    int hh = tid >> 4;
    int s0 = rp[dst], s1 = rp[dst + 1];
    float ad = __ldg(&aldst[dst * 8 + hh]);
    float4 acc = make_float4(0.f, 0.f, 0.f, 0.f);
    float esum = 0.f;
    for (int i = s0; i < s1; i++) {
        int src = __ldg(&csrc[i]);
        float al = __ldg(&alsrc[src * 8 + hh]);
        float v = al + ad;
        v = v > 0.f ? v : 0.2f * v;
        float e = expf(v);
        esum += e;
        float4 vv = *(const float4*)(hw + ((size_t)src << 9) + (tid << 2));
        acc.x += e * vv.x; acc.y += e * vv.y; acc.z += e * vv.z; acc.w += e * vv.w;
    }
    float siv = __frcp_rn(esum);
    acc.x *= siv; acc.y *= siv; acc.z *= siv; acc.w *= siv;
    float4 bb = *(const float4*)(bias + (tid << 2));
    float4 r;
    r.x = gelu(acc.x + bb.x);
    r.y = gelu(acc.y + bb.y);
    r.z = gelu(acc.z + bb.z);
    r.w = gelu(acc.w + bb.w);
    float* hrow = h + ((size_t)dst << 9) + (tid << 2);
    if (addRes) {
        float4 old = *(const float4*)hrow;
        r.x += old.x; r.y += old.y; r.z += old.z; r.w += old.w;
    }
    *(float4*)hrow = r;

    float p1 = r.x + r.y + r.z + r.w;
    float p2 = r.x * r.x + r.y * r.y + r.z * r.z + r.w * r.w;
    __shared__ float sh1[4], sh2[4];
    for (int o = 16; o > 0; o >>= 1) {
        p1 += __shfl_down_sync(0xffffffffu, p1, o);
        p2 += __shfl_down_sync(0xffffffffu, p2, o);
    }
    int w = tid >> 5, l = tid & 31;
    if (l == 0) { sh1[w] = p1; sh2[w] = p2; }
    __syncthreads();
    if (tid == 0) {
        sh1[0] = sh1[0] + sh1[1] + sh1[2] + sh1[3];
        sh2[0] = sh2[0] + sh2[1] + sh2[2] + sh2[3];
    }
    __syncthreads();
    float mean = sh1[0] * (1.0f / 512.0f);
    float var  = sh2[0] * (1.0f / 512.0f) - mean * mean;
    float rstd = rsqrtf(var + 1e-6f);
    float4 gg = *(const float4*)(lg + (tid << 2));
    float4 bv = *(const float4*)(lb + (tid << 2));
    float4 o4;
    o4.x = (r.x - mean) * rstd * gg.x + bv.x;
    o4.y = (r.y - mean) * rstd * gg.y + bv.y;
    o4.z = (r.z - mean) * rstd * gg.z + bv.z;
    o4.w = (r.w - mean) * rstd * gg.w + bv.w;
    *(float4*)(lnout + ((size_t)dst << 9) + (tid << 2)) = o4;
}

// ---------------- layer 3 tiny GEMM + logits ----------------
__global__ void gemm3_kernel(const float* __restrict__ ln, const float* __restrict__ W,
                             const float* __restrict__ asr, const float* __restrict__ adt,
                             float* hw3, float* alsrc, float* aldst) {
    int n = blockIdx.x, t = threadIdx.x;
    const float* row = ln + (size_t)n * 512;
    float p0 = 0.f, p1 = 0.f, p2 = 0.f;
    for (int k = t; k < 512; k += 128) {
        float a = row[k];
        p0 += a * W[k];
        p1 += a * W[512 + k];
        p2 += a * W[1024 + k];
    }
    __shared__ float sh[3][4];
    for (int o = 16; o > 0; o >>= 1) {
        p0 += __shfl_down_sync(0xffffffffu, p0, o);
        p1 += __shfl_down_sync(0xffffffffu, p1, o);
        p2 += __shfl_down_sync(0xffffffffu, p2, o);
    }
    int w = t >> 5, l = t & 31;
    if (l == 0) { sh[0][w] = p0; sh[1][w] = p1; sh[2][w] = p2; }
    __syncthreads();
    if (t == 0) {
        float v0 = sh[0][0] + sh[0][1] + sh[0][2] + sh[0][3];
        float v1 = sh[1][0] + sh[1][1] + sh[1][2] + sh[1][3];
        float v2 = sh[2][0] + sh[2][1] + sh[2][2] + sh[2][3];
        hw3[n * 3 + 0] = v0; hw3[n * 3 + 1] = v1; hw3[n * 3 + 2] = v2;
        alsrc[n] = v0 * asr[0] + v1 * asr[1] + v2 * asr[2];
        aldst[n] = v0 * adt[0] + v1 * adt[1] + v2 * adt[2];
    }
}

// ---------------- final gather ----------------
__global__ void final_gather(const int* __restrict__ rp, const int* __restrict__ csrc,
                             const float* __restrict__ alsrc, const float* __restrict__ aldst,
                             const float* __restrict__ hw3, const float* __restrict__ b3,
                             const float* __restrict__ res, float* __restrict__ out) {
    int dst = blockIdx.x * blockDim.x + threadIdx.x;
    if (dst >= NN) return;
    int s0 = rp[dst], s1 = rp[dst + 1];
    float ad = aldst[dst];
    float esum = 0.f;
    float a0 = 0.f, a1 = 0.f, a2 = 0.f;
    for (int i = s0; i < s1; i++) {
        int src = __ldg(&csrc[i]);
        float v = __ldg(&alsrc[src]) + ad;
        v = v > 0.f ? v : 0.2f * v;
        float e = expf(v);
        esum += e;
        a0 += e * __ldg(&hw3[src * 3 + 0]);
        a1 += e * __ldg(&hw3[src * 3 + 1]);
        a2 += e * __ldg(&hw3[src * 3 + 2]);
    }
    float siv = __frcp_rn(esum);
    out[dst * 3 + 0] = a0 * siv + b3[0] + res[dst * 3 + 0];
    out[dst * 3 + 1] = a1 * siv + b3[1] + res[dst * 3 + 1];
    out[dst * 3 + 2] = a2 * siv + b3[2] + res[dst * 3 + 2];
}

// ---------------- input residual ----------------
__global__ void resid_kernel(const float* __restrict__ x, const float* __restrict__ rw,
                             const float* __restrict__ rb, float* res) {
    int n = blockIdx.x, t = threadIdx.x;
    float a = x[(size_t)n * 128 + t];
    float p0 = a * rw[t], p1 = a * rw[128 + t], p2 = a * rw[256 + t];
    __shared__ float sh[3][4];
    for (int o = 16; o > 0; o >>= 1) {
        p0 += __shfl_down_sync(0xffffffffu, p0, o);
        p1 += __shfl_down_sync(0xffffffffu, p1, o);
        p2 += __shfl_down_sync(0xffffffffu, p2, o);
    }
    int w = t >> 5, l = t & 31;
    if (l == 0) { sh[0][w] = p0; sh[1][w] = p1; sh[2][w] = p2; }
    __syncthreads();
    if (t == 0) {
        res[n * 3 + 0] = sh[0][0] + sh[0][1] + sh[0][2] + sh[0][3] + rb[0];
        res[n * 3 + 1] = sh[1][0] + sh[1][1] + sh[1][2] + sh[1][3] + rb[1];
        res[n * 3 + 2] = sh[2][0] + sh[2][1] + sh[2][2] + sh[2][3] + rb[2];
    }
}

// ---------------- launch ----------------
extern "C" void kernel_launch(void* const* d_in, const int* in_sizes, int n_in,
                              void* d_out, int out_size) {
    const float* x    = (const float*)d_in[0];
    const int*   ei   = (const int*)d_in[1];
    const float* resW = (const float*)d_in[2];
    const float* resb = (const float*)d_in[3];

    const float* lng[4];  const float* lnb[4];
    const float* Wl[4];   const float* asr[4];
    const float* adt[4];  const float* bl[4];
    for (int l = 0; l < 4; l++) {
        int base = 4 + 6 * l;
        lng[l] = (const float*)d_in[base + 0];
        lnb[l] = (const float*)d_in[base + 1];
        Wl[l]  = (const float*)d_in[base + 2];
        asr[l] = (const float*)d_in[base + 3];
        adt[l] = (const float*)d_in[base + 4];
        bl[l]  = (const float*)d_in[base + 5];
    }

    float *ln_, *hw_, *h_, *alsrc_, *aldst_, *res_;
    int *deg_, *rp_, *cur_, *csrc_;
    cudaGetSymbolAddress((void**)&ln_,    g_ln);
    cudaGetSymbolAddress((void**)&hw_,    g_hw);
    cudaGetSymbolAddress((void**)&h_,     g_h);
    cudaGetSymbolAddress((void**)&alsrc_, g_alsrc);
    cudaGetSymbolAddress((void**)&aldst_, g_aldst);
    cudaGetSymbolAddress((void**)&res_,   g_res);
    cudaGetSymbolAddress((void**)&deg_,   g_deg);
    cudaGetSymbolAddress((void**)&rp_,    g_rowptr);
    cudaGetSymbolAddress((void**)&cur_,   g_cursor);
    cudaGetSymbolAddress((void**)&csrc_,  g_csrc);

    // launch order: ncu capture (launch #4) lands on gemm_tf32
    resid_kernel<<<NN, 128>>>(x, resW, resb, res_);                       // 1
    ln_kernel<<<NN, 128>>>(x, lng[0], lnb[0], ln_, CIN);                  // 2
    zero_deg_kernel<<<(NN + 255) / 256, 256>>>(deg_);                     // 3
    gemm_tf32<<<dim3(HC / BN, NP / BM), 128>>>(ln_, Wl[0], hw_, NN, CIN, HC,
                                               asr[0], adt[0], alsrc_, aldst_);  // 4 <- profiled
    deg_kernel<<<(EP + 255) / 256, 256>>>(ei, deg_);                      // 5
    scan_kernel<<<1, 1024>>>(deg_, rp_, cur_);                            // 6
    scatter_kernel<<<(EP + 255) / 256, 256>>>(ei, cur_, csrc_);           // 7

    msgB_kernel<<<NN, 128>>>(rp_, csrc_, alsrc_, aldst_, hw_, bl[0],
                             lng[1], lnb[1], h_, ln_, 0);

    for (int l = 1; l < 3; l++) {
        gemm_tf32<<<dim3(HC / BN, NP / BM), 128>>>(ln_, Wl[l], hw_, NN, HC, HC,
                                                   asr[l], adt[l], alsrc_, aldst_);
        msgB_kernel<<<NN, 128>>>(rp_, csrc_, alsrc_, aldst_, hw_, bl[l],
                                 lng[l + 1], lnb[l + 1], h_, ln_, 1);
    }

    gemm3_kernel<<<NN, 128>>>(ln_, Wl[3], asr[3], adt[3], hw_, alsrc_, aldst_);
    final_gather<<<(NN + 255) / 256, 256>>>(rp_, csrc_, alsrc_, aldst_, hw_, bl[3], res_, (float*)d_out);
}

// round 16
// speedup vs baseline: 1.1020x; 1.0350x over previous
#include <cuda_runtime.h>
#include <cuda_fp16.h>
#include <mma.h>
#include <math.h>

using namespace nvcuda;

#define NN   50000
#define NP   50048
#define EE   400000
#define EP   450000
#define CIN  128
#define HID  64
#define HEADS 8
#define HC   512
#define OUTD 3

// ---------------- scratch ----------------
__device__ float  g_ln[NP * HC];
__device__ float  g_hw[NP * HC];       // fp32 GEMM output (staging + layer-3 use)
__device__ __half g_hwh[NP * HC];      // fp16 message payload
__device__ float  g_h[NN * HC];
__device__ float  g_alsrc[NN * HEADS];
__device__ float  g_aldst[NN * HEADS];
__device__ float  g_res[NN * OUTD];
__device__ int    g_deg[NN];
__device__ int    g_rowptr[NN + 1];
__device__ int    g_cursor[NN];
__device__ int    g_csrc[EP];

// ---------------- helpers ----------------
__device__ __forceinline__ void cpAsync16(unsigned dst, const void* src, int srcBytes) {
    asm volatile("cp.async.ca.shared.global [%0], [%1], 16, %2;"
                 :: "r"(dst), "l"(src), "r"(srcBytes));
}

__device__ __forceinline__ float gelu(float v) {
    return 0.5f * v * (1.0f + erff(v * 0.70710678118654752f));
}

// ---------------- CSR build ----------------
__global__ void zero_deg_kernel(int* deg) {
    int i = blockIdx.x * blockDim.x + threadIdx.x;
    if (i < NN) deg[i] = 0;
}

__global__ void deg_kernel(const int* __restrict__ ei, int* deg) {
    int e = blockIdx.x * blockDim.x + threadIdx.x;
    if (e >= EP) return;
    int dst = (e < EE) ? ei[EE + e] : e - EE;
    atomicAdd(&deg[dst], 1);
}

__global__ void scan_kernel(const int* __restrict__ deg, int* rowptr, int* cursor) {
    const int T = 1024;
    const int CH = (NN + T - 1) / T;
    int t = threadIdx.x;
    int base = t * CH;
    int s = 0;
    for (int i = 0; i < CH; i++) {
        int j = base + i;
        if (j < NN) s += deg[j];
    }
    __shared__ int sh[T];
    sh[t] = s;
    __syncthreads();
    for (int o = 1; o < T; o <<= 1) {
        int v = (t >= o) ? sh[t - o] : 0;
        __syncthreads();
        sh[t] += v;
        __syncthreads();
    }
    int run = (t > 0) ? sh[t - 1] : 0;
    for (int i = 0; i < CH; i++) {
        int j = base + i;
        if (j < NN) { rowptr[j] = run; cursor[j] = run; run += deg[j]; }
    }
    if (t == T - 1) rowptr[NN] = run;
}

__global__ void scatter_kernel(const int* __restrict__ ei, int* cursor, int* csrc) {
    int e = blockIdx.x * blockDim.x + threadIdx.x;
    if (e >= EP) return;
    int src, dst;
    if (e < EE) { src = ei[e]; dst = ei[EE + e]; } else { src = dst = e - EE; }
    int pos = atomicAdd(&cursor[dst], 1);
    csrc[pos] = src;
}

// ---------------- LayerNorm (raw input x only) ----------------
__global__ void ln_kernel(const float* __restrict__ x, const float* __restrict__ g,
                          const float* __restrict__ b, float* __restrict__ out, int ci) {
    int n = blockIdx.x;
    const float* row = x + (size_t)n * ci;
    float s1 = 0.f, s2 = 0.f;
    for (int k = threadIdx.x; k < ci; k += 128) {
        float v = row[k];
        s1 += v; s2 += v * v;
    }
    __shared__ float sh1[4], sh2[4];
    for (int o = 16; o > 0; o >>= 1) {
        s1 += __shfl_down_sync(0xffffffffu, s1, o);
        s2 += __shfl_down_sync(0xffffffffu, s2, o);
    }
    int w = threadIdx.x >> 5, l = threadIdx.x & 31;
    if (l == 0) { sh1[w] = s1; sh2[w] = s2; }
    __syncthreads();
    if (threadIdx.x == 0) {
        float a = 0.f, c = 0.f;
        for (int i = 0; i < 4; i++) { a += sh1[i]; c += sh2[i]; }
        sh1[0] = a; sh2[0] = c;
    }
    __syncthreads();
    float inv = 1.0f / (float)ci;
    float mean = sh1[0] * inv;
    float var  = sh2[0] * inv - mean * mean;
    float rstd = rsqrtf(var + 1e-6f);
    float* orow = out + (size_t)n * ci;
    for (int k = threadIdx.x; k < ci; k += 128)
        orow[k] = (row[k] - mean) * rstd * g[k] + b[k];
}

// ---------------- tf32 GEMM: 4 warps x (64x64), 2-stage; epilogue: logits + fp16 copy ----------------
#define BM 128
#define BN 128
#define BK 16
#define SPAD 4
#define SLD (BK + SPAD)   // 20 floats

__global__ void __launch_bounds__(128, 2) gemm_tf32(
                          const float* __restrict__ A, const float* __restrict__ B,
                          float* __restrict__ C, __half* __restrict__ Ch,
                          int M, int K, int Nc,
                          const float* __restrict__ asr, const float* __restrict__ adt,
                          float* __restrict__ alsrc, float* __restrict__ aldst) {
    __shared__ __align__(16) float As[2][BM][SLD];
    __shared__ __align__(16) float Bs[2][BN][SLD];
    int tid = threadIdx.x;
    int warp = tid >> 5;
    int wm = warp >> 1;
    int wn = warp & 1;
    int rowBase = blockIdx.y * BM;
    int colBase = blockIdx.x * BN;

    wmma::fragment<wmma::accumulator, 16, 16, 8, float> acc[4][4];
    #pragma unroll
    for (int i = 0; i < 4; i++)
        #pragma unroll
        for (int j = 0; j < 4; j++) wmma::fill_fragment(acc[i][j], 0.f);

    int nIter = K / BK;

    int r = tid >> 2;
    int c = (tid & 3) * 4;
    auto loadStage = [&](int s, int it) {
        int k0 = it * BK;
        #pragma unroll
        for (int i = 0; i < 4; i++) {
            int rr = r + i * 32;
            int gr = rowBase + rr;
            unsigned da = (unsigned)__cvta_generic_to_shared(&As[s][rr][c]);
            cpAsync16(da, A + (size_t)gr * K + k0 + c, gr < M ? 16 : 0);
            unsigned db = (unsigned)__cvta_generic_to_shared(&Bs[s][rr][c]);
            cpAsync16(db, B + (size_t)(colBase + rr) * K + k0 + c, 16);
        }
        asm volatile("cp.async.commit_group;");
    };

    loadStage(0, 0);

    for (int it = 0; it < nIter; it++) {
        int buf = it & 1;
        if (it + 1 < nIter) {
            loadStage(buf ^ 1, it + 1);
            asm volatile("cp.async.wait_group 1;");
        } else {
            asm volatile("cp.async.wait_group 0;");
        }
        __syncthreads();
        #pragma unroll
        for (int kk = 0; kk < BK; kk += 8) {
            wmma::fragment<wmma::matrix_a, 16, 16, 8, wmma::precision::tf32, wmma::row_major> af[4];
            wmma::fragment<wmma::matrix_b, 16, 16, 8, wmma::precision::tf32, wmma::col_major> bf[4];
            #pragma unroll
            for (int i = 0; i < 4; i++)
                wmma::load_matrix_sync(af[i], &As[buf][wm * 64 + i * 16][kk], SLD);
            #pragma unroll
            for (int j = 0; j < 4; j++)
                wmma::load_matrix_sync(bf[j], &Bs[buf][wn * 64 + j * 16][kk], SLD);
            #pragma unroll
            for (int i = 0; i < 4; i++)
                #pragma unroll
                for (int j = 0; j < 4; j++)
                    wmma::mma_sync(acc[i][j], af[i], bf[j], acc[i][j]);
        }
        __syncthreads();
    }
    #pragma unroll
    for (int i = 0; i < 4; i++)
        #pragma unroll
        for (int j = 0; j < 4; j++) {
            int rr = rowBase + wm * 64 + i * 16;
            int cc = colBase + wn * 64 + j * 16;
            wmma::store_matrix_sync(C + (size_t)rr * Nc + cc, acc[i][j], Nc, wmma::mem_row_major);
        }

    // ---- fused epilogue: attn logits + fp16 payload copy ----
    __threadfence_block();
    __syncthreads();
    int lane = tid & 31;
    int half = lane >> 4;
    int lc = (lane & 15) * 4;
    int head = (colBase >> 6) + half;
    float4 wa = *(const float4*)(asr + head * 64 + lc);
    float4 wd = *(const float4*)(adt + head * 64 + lc);
    #pragma unroll
    for (int rr = 0; rr < 32; rr++) {
        int grow = rowBase + warp * 32 + rr;
        size_t off = (size_t)grow * Nc + colBase + half * 64 + lc;
        float4 cv = *(const float4*)(C + off);
        // fp16 copy (coalesced 8B per lane)
        __half2 h0 = __floats2half2_rn(cv.x, cv.y);
        __half2 h1 = __floats2half2_rn(cv.z, cv.w);
        uint2 packed;
        packed.x = *(unsigned*)&h0;
        packed.y = *(unsigned*)&h1;
        *(uint2*)(Ch + off) = packed;
        float s1 = cv.x * wa.x + cv.y * wa.y + cv.z * wa.z + cv.w * wa.w;
        float s2 = cv.x * wd.x + cv.y * wd.y + cv.z * wd.z + cv.w * wd.w;
        #pragma unroll
        for (int o = 8; o > 0; o >>= 1) {
            s1 += __shfl_xor_sync(0xffffffffu, s1, o);
            s2 += __shfl_xor_sync(0xffffffffu, s2, o);
        }
        if ((lane & 15) == 0 && grow < NN) {
            alsrc[grow * HEADS + head] = s1;
            aldst[grow * HEADS + head] = s2;
        }
    }
}

// ---------------- fused gather: softmax + agg(fp16 payload) + bias + gelu + residual + next-LN ----------------
__global__ void msgB_kernel(const int* __restrict__ rp, const int* __restrict__ csrc,
                            const float* __restrict__ alsrc, const float* __restrict__ aldst,
                            const __half* __restrict__ hwh, const float* __restrict__ bias,
                            const float* __restrict__ lg, const float* __restrict__ lb,
                            float* __restrict__ h, float* __restrict__ lnout, int addRes) {
    int dst = blockIdx.x;
    int tid = threadIdx.x;
    int hh = tid >> 4;
    int s0 = rp[dst], s1 = rp[dst + 1];
    float ad = __ldg(&aldst[dst * 8 + hh]);
    float4 acc = make_float4(0.f, 0.f, 0.f, 0.f);
    float esum = 0.f;
    for (int i = s0; i < s1; i++) {
        int src = __ldg(&csrc[i]);
        float al = __ldg(&alsrc[src * 8 + hh]);
        float v = al + ad;
        v = v > 0.f ? v : 0.2f * v;
        float e = expf(v);
        esum += e;
        uint2 raw = *(const uint2*)(hwh + ((size_t)src << 9) + (tid << 2));
        __half2 ha = *(__half2*)&raw.x;
        __half2 hb = *(__half2*)&raw.y;
        float2 f0 = __half22float2(ha);
        float2 f1 = __half22float2(hb);
        acc.x += e * f0.x; acc.y += e * f0.y; acc.z += e * f1.x; acc.w += e * f1.y;
    }
    float siv = __frcp_rn(esum);
    acc.x *= siv; acc.y *= siv; acc.z *= siv; acc.w *= siv;
    float4 bb = *(const float4*)(bias + (tid << 2));
    float4 r;
    r.x = gelu(acc.x + bb.x);
    r.y = gelu(acc.y + bb.y);
    r.z = gelu(acc.z + bb.z);
    r.w = gelu(acc.w + bb.w);
    float* hrow = h + ((size_t)dst << 9) + (tid << 2);
    if (addRes) {
        float4 old = *(const float4*)hrow;
        r.x += old.x; r.y += old.y; r.z += old.z; r.w += old.w;
    }
    *(float4*)hrow = r;

    float p1 = r.x + r.y + r.z + r.w;
    float p2 = r.x * r.x + r.y * r.y + r.z * r.z + r.w * r.w;
    __shared__ float sh1[4], sh2[4];
    for (int o = 16; o > 0; o >>= 1) {
        p1 += __shfl_down_sync(0xffffffffu, p1, o);
        p2 += __shfl_down_sync(0xffffffffu, p2, o);
    }
    int w = tid >> 5, l = tid & 31;
    if (l == 0) { sh1[w] = p1; sh2[w] = p2; }
    __syncthreads();
    if (tid == 0) {
        sh1[0] = sh1[0] + sh1[1] + sh1[2] + sh1[3];
        sh2[0] = sh2[0] + sh2[1] + sh2[2] + sh2[3];
    }
    __syncthreads();
    float mean = sh1[0] * (1.0f / 512.0f);
    float var  = sh2[0] * (1.0f / 512.0f) - mean * mean;
    float rstd = rsqrtf(var + 1e-6f);
    float4 gg = *(const float4*)(lg + (tid << 2));
    float4 bv = *(const float4*)(lb + (tid << 2));
    float4 o4;
    o4.x = (r.x - mean) * rstd * gg.x + bv.x;
    o4.y = (r.y - mean) * rstd * gg.y + bv.y;
    o4.z = (r.z - mean) * rstd * gg.z + bv.z;
    o4.w = (r.w - mean) * rstd * gg.w + bv.w;
    *(float4*)(lnout + ((size_t)dst << 9) + (tid << 2)) = o4;
}

// ---------------- layer 3 tiny GEMM + logits ----------------
__global__ void gemm3_kernel(const float* __restrict__ ln, const float* __restrict__ W,
                             const float* __restrict__ asr, const float* __restrict__ adt,
                             float* hw3, float* alsrc, float* aldst) {
    int n = blockIdx.x, t = threadIdx.x;
    const float* row = ln + (size_t)n * 512;
    float p0 = 0.f, p1 = 0.f, p2 = 0.f;
    for (int k = t; k < 512; k += 128) {
        float a = row[k];
        p0 += a * W[k];
        p1 += a * W[512 + k];
        p2 += a * W[1024 + k];
    }
    __shared__ float sh[3][4];
    for (int o = 16; o > 0; o >>= 1) {
        p0 += __shfl_down_sync(0xffffffffu, p0, o);
        p1 += __shfl_down_sync(0xffffffffu, p1, o);
        p2 += __shfl_down_sync(0xffffffffu, p2, o);
    }
    int w = t >> 5, l = t & 31;
    if (l == 0) { sh[0][w] = p0; sh[1][w] = p1; sh[2][w] = p2; }
    __syncthreads();
    if (t == 0) {
        float v0 = sh[0][0] + sh[0][1] + sh[0][2] + sh[0][3];
        float v1 = sh[1][0] + sh[1][1] + sh[1][2] + sh[1][3];
        float v2 = sh[2][0] + sh[2][1] + sh[2][2] + sh[2][3];
        hw3[n * 3 + 0] = v0; hw3[n * 3 + 1] = v1; hw3[n * 3 + 2] = v2;
        alsrc[n] = v0 * asr[0] + v1 * asr[1] + v2 * asr[2];
        aldst[n] = v0 * adt[0] + v1 * adt[1] + v2 * adt[2];
    }
}

// ---------------- final gather ----------------
__global__ void final_gather(const int* __restrict__ rp, const int* __restrict__ csrc,
                             const float* __restrict__ alsrc, const float* __restrict__ aldst,
                             const float* __restrict__ hw3, const float* __restrict__ b3,
                             const float* __restrict__ res, float* __restrict__ out) {
    int dst = blockIdx.x * blockDim.x + threadIdx.x;
    if (dst >= NN) return;
    int s0 = rp[dst], s1 = rp[dst + 1];
    float ad = aldst[dst];
    float esum = 0.f;
    float a0 = 0.f, a1 = 0.f, a2 = 0.f;
    for (int i = s0; i < s1; i++) {
        int src = __ldg(&csrc[i]);
        float v = __ldg(&alsrc[src]) + ad;
        v = v > 0.f ? v : 0.2f * v;
        float e = expf(v);
        esum += e;
        a0 += e * __ldg(&hw3[src * 3 + 0]);
        a1 += e * __ldg(&hw3[src * 3 + 1]);
        a2 += e * __ldg(&hw3[src * 3 + 2]);
    }
    float siv = __frcp_rn(esum);
    out[dst * 3 + 0] = a0 * siv + b3[0] + res[dst * 3 + 0];
    out[dst * 3 + 1] = a1 * siv + b3[1] + res[dst * 3 + 1];
    out[dst * 3 + 2] = a2 * siv + b3[2] + res[dst * 3 + 2];
}

// ---------------- input residual ----------------
__global__ void resid_kernel(const float* __restrict__ x, const float* __restrict__ rw,
                             const float* __restrict__ rb, float* res) {
    int n = blockIdx.x, t = threadIdx.x;
    float a = x[(size_t)n * 128 + t];
    float p0 = a * rw[t], p1 = a * rw[128 + t], p2 = a * rw[256 + t];
    __shared__ float sh[3][4];
    for (int o = 16; o > 0; o >>= 1) {
        p0 += __shfl_down_sync(0xffffffffu, p0, o);
        p1 += __shfl_down_sync(0xffffffffu, p1, o);
        p2 += __shfl_down_sync(0xffffffffu, p2, o);
    }
    int w = t >> 5, l = t & 31;
    if (l == 0) { sh[0][w] = p0; sh[1][w] = p1; sh[2][w] = p2; }
    __syncthreads();
    if (t == 0) {
        res[n * 3 + 0] = sh[0][0] + sh[0][1] + sh[0][2] + sh[0][3] + rb[0];
        res[n * 3 + 1] = sh[1][0] + sh[1][1] + sh[1][2] + sh[1][3] + rb[1];
        res[n * 3 + 2] = sh[2][0] + sh[2][1] + sh[2][2] + sh[2][3] + rb[2];
    }
}

// ---------------- launch ----------------
extern "C" void kernel_launch(void* const* d_in, const int* in_sizes, int n_in,
                              void* d_out, int out_size) {
    const float* x    = (const float*)d_in[0];
    const int*   ei   = (const int*)d_in[1];
    const float* resW = (const float*)d_in[2];
    const float* resb = (const float*)d_in[3];

    const float* lng[4];  const float* lnb[4];
    const float* Wl[4];   const float* asr[4];
    const float* adt[4];  const float* bl[4];
    for (int l = 0; l < 4; l++) {
        int base = 4 + 6 * l;
        lng[l] = (const float*)d_in[base + 0];
        lnb[l] = (const float*)d_in[base + 1];
        Wl[l]  = (const float*)d_in[base + 2];
        asr[l] = (const float*)d_in[base + 3];
        adt[l] = (const float*)d_in[base + 4];
        bl[l]  = (const float*)d_in[base + 5];
    }

    float *ln_, *hw_, *h_, *alsrc_, *aldst_, *res_;
    __half* hwh_;
    int *deg_, *rp_, *cur_, *csrc_;
    cudaGetSymbolAddress((void**)&ln_,    g_ln);
    cudaGetSymbolAddress((void**)&hw_,    g_hw);
    cudaGetSymbolAddress((void**)&hwh_,   g_hwh);
    cudaGetSymbolAddress((void**)&h_,     g_h);
    cudaGetSymbolAddress((void**)&alsrc_, g_alsrc);
    cudaGetSymbolAddress((void**)&aldst_, g_aldst);
    cudaGetSymbolAddress((void**)&res_,   g_res);
    cudaGetSymbolAddress((void**)&deg_,   g_deg);
    cudaGetSymbolAddress((void**)&rp_,    g_rowptr);
    cudaGetSymbolAddress((void**)&cur_,   g_cursor);
    cudaGetSymbolAddress((void**)&csrc_,  g_csrc);

    // launch order: ncu capture (launch #4) lands on gemm_tf32
    resid_kernel<<<NN, 128>>>(x, resW, resb, res_);                       // 1
    ln_kernel<<<NN, 128>>>(x, lng[0], lnb[0], ln_, CIN);                  // 2
    zero_deg_kernel<<<(NN + 255) / 256, 256>>>(deg_);                     // 3
    gemm_tf32<<<dim3(HC / BN, NP / BM), 128>>>(ln_, Wl[0], hw_, hwh_, NN, CIN, HC,
                                               asr[0], adt[0], alsrc_, aldst_);  // 4 <- profiled
    deg_kernel<<<(EP + 255) / 256, 256>>>(ei, deg_);                      // 5
    scan_kernel<<<1, 1024>>>(deg_, rp_, cur_);                            // 6
    scatter_kernel<<<(EP + 255) / 256, 256>>>(ei, cur_, csrc_);           // 7

    msgB_kernel<<<NN, 128>>>(rp_, csrc_, alsrc_, aldst_, hwh_, bl[0],
                             lng[1], lnb[1], h_, ln_, 0);

    for (int l = 1; l < 3; l++) {
        gemm_tf32<<<dim3(HC / BN, NP / BM), 128>>>(ln_, Wl[l], hw_, hwh_, NN, HC, HC,
                                                   asr[l], adt[l], alsrc_, aldst_);
        msgB_kernel<<<NN, 128>>>(rp_, csrc_, alsrc_, aldst_, hwh_, bl[l],
                                 lng[l + 1], lnb[l + 1], h_, ln_, 1);
    }

    gemm3_kernel<<<NN, 128>>>(ln_, Wl[3], asr[3], adt[3], hw_, alsrc_, aldst_);
    final_gather<<<(NN + 255) / 256, 256>>>(rp_, csrc_, alsrc_, aldst_, hw_, bl[3], res_, (float*)d_out);
}

// round 17
// speedup vs baseline: 1.6539x; 1.5008x over previous
#include <cuda_runtime.h>
#include <cuda_fp16.h>
#include <mma.h>
#include <math.h>

using namespace nvcuda;

#define NN   50000
#define NP   50048
#define EE   400000
#define EP   450000
#define CIN  128
#define HID  64
#define HEADS 8
#define HC   512
#define OUTD 3

// ---------------- scratch ----------------
__device__ __half g_lnh[NP * HC];      // fp16 LN output (GEMM A operand)
__device__ __half g_wh[HC * HC];       // fp16 weight staging
__device__ float  g_hw[NP * HC];       // fp32 GEMM output (layer-3 path + epilogue source)
__device__ __half g_hwh[NP * HC];      // fp16 message payload
__device__ float  g_h[NN * HC];
__device__ float  g_alsrc[NN * HEADS];
__device__ float  g_aldst[NN * HEADS];
__device__ float  g_res[NN * OUTD];
__device__ int    g_deg[NN];
__device__ int    g_rowptr[NN + 1];
__device__ int    g_cursor[NN];
__device__ int    g_csrc[EP];

// ---------------- helpers ----------------
__device__ __forceinline__ void cpAsync16(unsigned dst, const void* src, int srcBytes) {
    asm volatile("cp.async.ca.shared.global [%0], [%1], 16, %2;"
                 :: "r"(dst), "l"(src), "r"(srcBytes));
}

__device__ __forceinline__ float gelu(float v) {
    return 0.5f * v * (1.0f + erff(v * 0.70710678118654752f));
}

// ---------------- weight convert fp32 -> fp16 ----------------
__global__ void convw_kernel(const float* __restrict__ w, __half* __restrict__ wh, int n) {
    int i = blockIdx.x * blockDim.x + threadIdx.x;
    if (i < n) wh[i] = __float2half_rn(w[i]);
}

// ---------------- CSR build ----------------
__global__ void zero_deg_kernel(int* deg) {
    int i = blockIdx.x * blockDim.x + threadIdx.x;
    if (i < NN) deg[i] = 0;
}

__global__ void deg_kernel(const int* __restrict__ ei, int* deg) {
    int e = blockIdx.x * blockDim.x + threadIdx.x;
    if (e >= EP) return;
    int dst = (e < EE) ? ei[EE + e] : e - EE;
    atomicAdd(&deg[dst], 1);
}

__global__ void scan_kernel(const int* __restrict__ deg, int* rowptr, int* cursor) {
    const int T = 1024;
    const int CH = (NN + T - 1) / T;
    int t = threadIdx.x;
    int base = t * CH;
    int s = 0;
    for (int i = 0; i < CH; i++) {
        int j = base + i;
        if (j < NN) s += deg[j];
    }
    __shared__ int sh[T];
    sh[t] = s;
    __syncthreads();
    for (int o = 1; o < T; o <<= 1) {
        int v = (t >= o) ? sh[t - o] : 0;
        __syncthreads();
        sh[t] += v;
        __syncthreads();
    }
    int run = (t > 0) ? sh[t - 1] : 0;
    for (int i = 0; i < CH; i++) {
        int j = base + i;
        if (j < NN) { rowptr[j] = run; cursor[j] = run; run += deg[j]; }
    }
    if (t == T - 1) rowptr[NN] = run;
}

__global__ void scatter_kernel(const int* __restrict__ ei, int* cursor, int* csrc) {
    int e = blockIdx.x * blockDim.x + threadIdx.x;
    if (e >= EP) return;
    int src, dst;
    if (e < EE) { src = ei[e]; dst = ei[EE + e]; } else { src = dst = e - EE; }
    int pos = atomicAdd(&cursor[dst], 1);
    csrc[pos] = src;
}

// ---------------- LayerNorm (raw input x only) -> fp16 out ----------------
__global__ void ln_kernel(const float* __restrict__ x, const float* __restrict__ g,
                          const float* __restrict__ b, __half* __restrict__ out, int ci) {
    int n = blockIdx.x;
    const float* row = x + (size_t)n * ci;
    float s1 = 0.f, s2 = 0.f;
    for (int k = threadIdx.x; k < ci; k += 128) {
        float v = row[k];
        s1 += v; s2 += v * v;
    }
    __shared__ float sh1[4], sh2[4];
    for (int o = 16; o > 0; o >>= 1) {
        s1 += __shfl_down_sync(0xffffffffu, s1, o);
        s2 += __shfl_down_sync(0xffffffffu, s2, o);
    }
    int w = threadIdx.x >> 5, l = threadIdx.x & 31;
    if (l == 0) { sh1[w] = s1; sh2[w] = s2; }
    __syncthreads();
    if (threadIdx.x == 0) {
        float a = 0.f, c = 0.f;
        for (int i = 0; i < 4; i++) { a += sh1[i]; c += sh2[i]; }
        sh1[0] = a; sh2[0] = c;
    }
    __syncthreads();
    float inv = 1.0f / (float)ci;
    float mean = sh1[0] * inv;
    float var  = sh2[0] * inv - mean * mean;
    float rstd = rsqrtf(var + 1e-6f);
    __half* orow = out + (size_t)n * ci;
    for (int k = threadIdx.x; k < ci; k += 128)
        orow[k] = __float2half_rn((row[k] - mean) * rstd * g[k] + b[k]);
}

// ---------------- fp16 GEMM: 4 warps x (64x64), m16n16k16, 2-stage cp.async ----------------
#define BM 128
#define BN 128
#define BKH 32
#define SLDH (BKH + 8)   // 40 halves = 80B stride

__global__ void __launch_bounds__(128, 2) gemm_fp16(
                          const __half* __restrict__ A, const __half* __restrict__ B,
                          float* __restrict__ C, __half* __restrict__ Ch,
                          int M, int K, int Nc,
                          const float* __restrict__ asr, const float* __restrict__ adt,
                          float* __restrict__ alsrc, float* __restrict__ aldst) {
    __shared__ __align__(16) __half As[2][BM][SLDH];
    __shared__ __align__(16) __half Bs[2][BN][SLDH];
    int tid = threadIdx.x;
    int warp = tid >> 5;
    int wm = warp >> 1;
    int wn = warp & 1;
    int rowBase = blockIdx.y * BM;
    int colBase = blockIdx.x * BN;

    wmma::fragment<wmma::accumulator, 16, 16, 16, float> acc[4][4];
    #pragma unroll
    for (int i = 0; i < 4; i++)
        #pragma unroll
        for (int j = 0; j < 4; j++) wmma::fill_fragment(acc[i][j], 0.f);

    int nIter = K / BKH;

    // tile = 128 rows x 32 halves = 128 x 4 chunks of 16B; 128 threads -> 4 chunks each
    auto loadStage = [&](int s, int it) {
        int k0 = it * BKH;
        #pragma unroll
        for (int i = 0; i < 4; i++) {
            int idx = tid + i * 128;
            int row = idx >> 2;
            int ch = (idx & 3) * 8;    // half offset
            int gr = rowBase + row;
            unsigned da = (unsigned)__cvta_generic_to_shared(&As[s][row][ch]);
            cpAsync16(da, A + (size_t)gr * K + k0 + ch, gr < M ? 16 : 0);
            unsigned db = (unsigned)__cvta_generic_to_shared(&Bs[s][row][ch]);
            cpAsync16(db, B + (size_t)(colBase + row) * K + k0 + ch, 16);
        }
        asm volatile("cp.async.commit_group;");
    };

    loadStage(0, 0);

    for (int it = 0; it < nIter; it++) {
        int buf = it & 1;
        if (it + 1 < nIter) {
            loadStage(buf ^ 1, it + 1);
            asm volatile("cp.async.wait_group 1;");
        } else {
            asm volatile("cp.async.wait_group 0;");
        }
        __syncthreads();
        #pragma unroll
        for (int kk = 0; kk < BKH; kk += 16) {
            wmma::fragment<wmma::matrix_a, 16, 16, 16, __half, wmma::row_major> af[4];
            wmma::fragment<wmma::matrix_b, 16, 16, 16, __half, wmma::col_major> bf[4];
            #pragma unroll
            for (int i = 0; i < 4; i++)
                wmma::load_matrix_sync(af[i], &As[buf][wm * 64 + i * 16][kk], SLDH);
            #pragma unroll
            for (int j = 0; j < 4; j++)
                wmma::load_matrix_sync(bf[j], &Bs[buf][wn * 64 + j * 16][kk], SLDH);
            #pragma unroll
            for (int i = 0; i < 4; i++)
                #pragma unroll
                for (int j = 0; j < 4; j++)
                    wmma::mma_sync(acc[i][j], af[i], bf[j], acc[i][j]);
        }
        __syncthreads();
    }
    #pragma unroll
    for (int i = 0; i < 4; i++)
        #pragma unroll
        for (int j = 0; j < 4; j++) {
            int rr = rowBase + wm * 64 + i * 16;
            int cc = colBase + wn * 64 + j * 16;
            wmma::store_matrix_sync(C + (size_t)rr * Nc + cc, acc[i][j], Nc, wmma::mem_row_major);
        }

    // ---- fused epilogue: attn logits + fp16 payload copy ----
    __threadfence_block();
    __syncthreads();
    int lane = tid & 31;
    int half = lane >> 4;
    int lc = (lane & 15) * 4;
    int head = (colBase >> 6) + half;
    float4 wa = *(const float4*)(asr + head * 64 + lc);
    float4 wd = *(const float4*)(adt + head * 64 + lc);
    #pragma unroll
    for (int rr = 0; rr < 32; rr++) {
        int grow = rowBase + warp * 32 + rr;
        size_t off = (size_t)grow * Nc + colBase + half * 64 + lc;
        float4 cv = *(const float4*)(C + off);
        __half2 h0 = __floats2half2_rn(cv.x, cv.y);
        __half2 h1 = __floats2half2_rn(cv.z, cv.w);
        uint2 packed;
        packed.x = *(unsigned*)&h0;
        packed.y = *(unsigned*)&h1;
        *(uint2*)(Ch + off) = packed;
        float s1 = cv.x * wa.x + cv.y * wa.y + cv.z * wa.z + cv.w * wa.w;
        float s2 = cv.x * wd.x + cv.y * wd.y + cv.z * wd.z + cv.w * wd.w;
        #pragma unroll
        for (int o = 8; o > 0; o >>= 1) {
            s1 += __shfl_xor_sync(0xffffffffu, s1, o);
            s2 += __shfl_xor_sync(0xffffffffu, s2, o);
        }
        if ((lane & 15) == 0 && grow < NN) {
            alsrc[grow * HEADS + head] = s1;
            aldst[grow * HEADS + head] = s2;
        }
    }
}

// ---------------- fused gather: softmax + agg(fp16) + bias + gelu + residual + next-LN(fp16 out) ----------------
__global__ void msgB_kernel(const int* __restrict__ rp, const int* __restrict__ csrc,
                            const float* __restrict__ alsrc, const float* __restrict__ aldst,
                            const __half* __restrict__ hwh, const float* __restrict__ bias,
                            const float* __restrict__ lg, const float* __restrict__ lb,
                            float* __restrict__ h, __half* __restrict__ lnout, int addRes) {
    int dst = blockIdx.x;
    int tid = threadIdx.x;
    int hh = tid >> 4;
    int s0 = rp[dst], s1 = rp[dst + 1];
    float ad = __ldg(&aldst[dst * 8 + hh]);
    float4 acc = make_float4(0.f, 0.f, 0.f, 0.f);
    float esum = 0.f;
    for (int i = s0; i < s1; i++) {
        int src = __ldg(&csrc[i]);
        float al = __ldg(&alsrc[src * 8 + hh]);
        float v = al + ad;
        v = v > 0.f ? v : 0.2f * v;
        float e = expf(v);
        esum += e;
        uint2 raw = *(const uint2*)(hwh + ((size_t)src << 9) + (tid << 2));
        __half2 ha = *(__half2*)&raw.x;
        __half2 hb = *(__half2*)&raw.y;
        float2 f0 = __half22float2(ha);
        float2 f1 = __half22float2(hb);
        acc.x += e * f0.x; acc.y += e * f0.y; acc.z += e * f1.x; acc.w += e * f1.y;
    }
    float siv = __frcp_rn(esum);
    acc.x *= siv; acc.y *= siv; acc.z *= siv; acc.w *= siv;
    float4 bb = *(const float4*)(bias + (tid << 2));
    float4 r;
    r.x = gelu(acc.x + bb.x);
    r.y = gelu(acc.y + bb.y);
    r.z = gelu(acc.z + bb.z);
    r.w = gelu(acc.w + bb.w);
    float* hrow = h + ((size_t)dst << 9) + (tid << 2);
    if (addRes) {
        float4 old = *(const float4*)hrow;
        r.x += old.x; r.y += old.y; r.z += old.z; r.w += old.w;
    }
    *(float4*)hrow = r;

    float p1 = r.x + r.y + r.z + r.w;
    float p2 = r.x * r.x + r.y * r.y + r.z * r.z + r.w * r.w;
    __shared__ float sh1[4], sh2[4];
    for (int o = 16; o > 0; o >>= 1) {
        p1 += __shfl_down_sync(0xffffffffu, p1, o);
        p2 += __shfl_down_sync(0xffffffffu, p2, o);
    }
    int w = tid >> 5, l = tid & 31;
    if (l == 0) { sh1[w] = p1; sh2[w] = p2; }
    __syncthreads();
    if (tid == 0) {
        sh1[0] = sh1[0] + sh1[1] + sh1[2] + sh1[3];
        sh2[0] = sh2[0] + sh2[1] + sh2[2] + sh2[3];
    }
    __syncthreads();
    float mean = sh1[0] * (1.0f / 512.0f);
    float var  = sh2[0] * (1.0f / 512.0f) - mean * mean;
    float rstd = rsqrtf(var + 1e-6f);
    float4 gg = *(const float4*)(lg + (tid << 2));
    float4 bv = *(const float4*)(lb + (tid << 2));
    __half2 o0 = __floats2half2_rn((r.x - mean) * rstd * gg.x + bv.x,
                                   (r.y - mean) * rstd * gg.y + bv.y);
    __half2 o1 = __floats2half2_rn((r.z - mean) * rstd * gg.z + bv.z,
                                   (r.w - mean) * rstd * gg.w + bv.w);
    uint2 packed;
    packed.x = *(unsigned*)&o0;
    packed.y = *(unsigned*)&o1;
    *(uint2*)(lnout + ((size_t)dst << 9) + (tid << 2)) = packed;
}

// ---------------- layer 3 tiny GEMM (fp16 ln input) + logits ----------------
__global__ void gemm3_kernel(const __half* __restrict__ ln, const float* __restrict__ W,
                             const float* __restrict__ asr, const float* __restrict__ adt,
                             float* hw3, float* alsrc, float* aldst) {
    int n = blockIdx.x, t = threadIdx.x;
    const __half* row = ln + (size_t)n * 512;
    float p0 = 0.f, p1 = 0.f, p2 = 0.f;
    for (int k = t; k < 512; k += 128) {
        float a = __half2float(row[k]);
        p0 += a * W[k];
        p1 += a * W[512 + k];
        p2 += a * W[1024 + k];
    }
    __shared__ float sh[3][4];
    for (int o = 16; o > 0; o >>= 1) {
        p0 += __shfl_down_sync(0xffffffffu, p0, o);
        p1 += __shfl_down_sync(0xffffffffu, p1, o);
        p2 += __shfl_down_sync(0xffffffffu, p2, o);
    }
    int w = t >> 5, l = t & 31;
    if (l == 0) { sh[0][w] = p0; sh[1][w] = p1; sh[2][w] = p2; }
    __syncthreads();
    if (t == 0) {
        float v0 = sh[0][0] + sh[0][1] + sh[0][2] + sh[0][3];
        float v1 = sh[1][0] + sh[1][1] + sh[1][2] + sh[1][3];
        float v2 = sh[2][0] + sh[2][1] + sh[2][2] + sh[2][3];
        hw3[n * 3 + 0] = v0; hw3[n * 3 + 1] = v1; hw3[n * 3 + 2] = v2;
        alsrc[n] = v0 * asr[0] + v1 * asr[1] + v2 * asr[2];
        aldst[n] = v0 * adt[0] + v1 * adt[1] + v2 * adt[2];
    }
}

// ---------------- final gather ----------------
__global__ void final_gather(const int* __restrict__ rp, const int* __restrict__ csrc,
                             const float* __restrict__ alsrc, const float* __restrict__ aldst,
                             const float* __restrict__ hw3, const float* __restrict__ b3,
                             const float* __restrict__ res, float* __restrict__ out) {
    int dst = blockIdx.x * blockDim.x + threadIdx.x;
    if (dst >= NN) return;
    int s0 = rp[dst], s1 = rp[dst + 1];
    float ad = aldst[dst];
    float esum = 0.f;
    float a0 = 0.f, a1 = 0.f, a2 = 0.f;
    for (int i = s0; i < s1; i++) {
        int src = __ldg(&csrc[i]);
        float v = __ldg(&alsrc[src]) + ad;
        v = v > 0.f ? v : 0.2f * v;
        float e = expf(v);
        esum += e;
        a0 += e * __ldg(&hw3[src * 3 + 0]);
        a1 += e * __ldg(&hw3[src * 3 + 1]);
        a2 += e * __ldg(&hw3[src * 3 + 2]);
    }
    float siv = __frcp_rn(esum);
    out[dst * 3 + 0] = a0 * siv + b3[0] + res[dst * 3 + 0];
    out[dst * 3 + 1] = a1 * siv + b3[1] + res[dst * 3 + 1];
    out[dst * 3 + 2] = a2 * siv + b3[2] + res[dst * 3 + 2];
}

// ---------------- input residual ----------------
__global__ void resid_kernel(const float* __restrict__ x, const float* __restrict__ rw,
                             const float* __restrict__ rb, float* res) {
    int n = blockIdx.x, t = threadIdx.x;
    float a = x[(size_t)n * 128 + t];
    float p0 = a * rw[t], p1 = a * rw[128 + t], p2 = a * rw[256 + t];
    __shared__ float sh[3][4];
    for (int o = 16; o > 0; o >>= 1) {
        p0 += __shfl_down_sync(0xffffffffu, p0, o);
        p1 += __shfl_down_sync(0xffffffffu, p1, o);
        p2 += __shfl_down_sync(0xffffffffu, p2, o);
    }
    int w = t >> 5, l = t & 31;
    if (l == 0) { sh[0][w] = p0; sh[1][w] = p1; sh[2][w] = p2; }
    __syncthreads();
    if (t == 0) {
        res[n * 3 + 0] = sh[0][0] + sh[0][1] + sh[0][2] + sh[0][3] + rb[0];
        res[n * 3 + 1] = sh[1][0] + sh[1][1] + sh[1][2] + sh[1][3] + rb[1];
        res[n * 3 + 2] = sh[2][0] + sh[2][1] + sh[2][2] + sh[2][3] + rb[2];
    }
}

// ---------------- launch ----------------
extern "C" void kernel_launch(void* const* d_in, const int* in_sizes, int n_in,
                              void* d_out, int out_size) {
    const float* x    = (const float*)d_in[0];
    const int*   ei   = (const int*)d_in[1];
    const float* resW = (const float*)d_in[2];
    const float* resb = (const float*)d_in[3];

    const float* lng[4];  const float* lnb[4];
    const float* Wl[4];   const float* asr[4];
    const float* adt[4];  const float* bl[4];
    for (int l = 0; l < 4; l++) {
        int base = 4 + 6 * l;
        lng[l] = (const float*)d_in[base + 0];
        lnb[l] = (const float*)d_in[base + 1];
        Wl[l]  = (const float*)d_in[base + 2];
        asr[l] = (const float*)d_in[base + 3];
        adt[l] = (const float*)d_in[base + 4];
        bl[l]  = (const float*)d_in[base + 5];
    }

    float *hw_, *h_, *alsrc_, *aldst_, *res_;
    __half *lnh_, *wh_, *hwh_;
    int *deg_, *rp_, *cur_, *csrc_;
    cudaGetSymbolAddress((void**)&lnh_,   g_lnh);
    cudaGetSymbolAddress((void**)&wh_,    g_wh);
    cudaGetSymbolAddress((void**)&hw_,    g_hw);
    cudaGetSymbolAddress((void**)&hwh_,   g_hwh);
    cudaGetSymbolAddress((void**)&h_,     g_h);
    cudaGetSymbolAddress((void**)&alsrc_, g_alsrc);
    cudaGetSymbolAddress((void**)&aldst_, g_aldst);
    cudaGetSymbolAddress((void**)&res_,   g_res);
    cudaGetSymbolAddress((void**)&deg_,   g_deg);
    cudaGetSymbolAddress((void**)&rp_,    g_rowptr);
    cudaGetSymbolAddress((void**)&cur_,   g_cursor);
    cudaGetSymbolAddress((void**)&csrc_,  g_csrc);

    // launch order: ncu capture (launch #4) lands on gemm_fp16
    resid_kernel<<<NN, 128>>>(x, resW, resb, res_);                       // 1
    ln_kernel<<<NN, 128>>>(x, lng[0], lnb[0], lnh_, CIN);                 // 2
    convw_kernel<<<(HC * CIN + 255) / 256, 256>>>(Wl[0], wh_, HC * CIN);  // 3
    gemm_fp16<<<dim3(HC / BN, NP / BM), 128>>>(lnh_, wh_, hw_, hwh_, NN, CIN, HC,
                                               asr[0], adt[0], alsrc_, aldst_);  // 4 <- profiled
    zero_deg_kernel<<<(NN + 255) / 256, 256>>>(deg_);                     // 5
    deg_kernel<<<(EP + 255) / 256, 256>>>(ei, deg_);                      // 6
    scan_kernel<<<1, 1024>>>(deg_, rp_, cur_);                            // 7
    scatter_kernel<<<(EP + 255) / 256, 256>>>(ei, cur_, csrc_);           // 8

    msgB_kernel<<<NN, 128>>>(rp_, csrc_, alsrc_, aldst_, hwh_, bl[0],
                             lng[1], lnb[1], h_, lnh_, 0);

    for (int l = 1; l < 3; l++) {
        convw_kernel<<<(HC * HC + 255) / 256, 256>>>(Wl[l], wh_, HC * HC);
        gemm_fp16<<<dim3(HC / BN, NP / BM), 128>>>(lnh_, wh_, hw_, hwh_, NN, HC, HC,
                                                   asr[l], adt[l], alsrc_, aldst_);
        msgB_kernel<<<NN, 128>>>(rp_, csrc_, alsrc_, aldst_, hwh_, bl[l],
                                 lng[l + 1], lnb[l + 1], h_, lnh_, 1);
    }

    gemm3_kernel<<<NN, 128>>>(lnh_, Wl[3], asr[3], adt[3], hw_, alsrc_, aldst_);
    final_gather<<<(NN + 255) / 256, 256>>>(rp_, csrc_, alsrc_, aldst_, hw_, bl[3], res_, (float*)d_out);
}